// round 1
// baseline (speedup 1.0000x reference)
#include <cuda_runtime.h>

// Problem constants (ParacrineCascade: B=32, N=2048, D=128, K=3)
#define B_   32
#define N_   2048
#define D_   128
#define TILE 128
#define KC   16
#define NT   256
#define ASTR (TILE + 4)   // padded smem row stride (floats)

// Scratch for per-point squared norms (no cudaMalloc allowed)
__device__ float g_sq[B_ * N_];

// ---------------------------------------------------------------------------
// Kernel 1: per-row squared norm, one warp per point.
// ---------------------------------------------------------------------------
__global__ void sq_kernel(const float* __restrict__ X) {
    int gw   = (blockIdx.x * blockDim.x + threadIdx.x) >> 5;
    int lane = threadIdx.x & 31;
    if (gw >= B_ * N_) return;
    const float4* x4 = reinterpret_cast<const float4*>(X) + (size_t)gw * (D_ / 4);
    float4 v = x4[lane];
    float s = v.x * v.x + v.y * v.y + v.z * v.z + v.w * v.w;
    #pragma unroll
    for (int off = 16; off; off >>= 1) s += __shfl_xor_sync(0xffffffffu, s, off);
    if (lane == 0) g_sq[gw] = s;
}

// Insert (s, m) into a sorted ascending top-3 list.
__device__ __forceinline__ void ins3(float s, int m,
                                     float& t0, float& t1, float& t2,
                                     int& i0, int& i1, int& i2) {
    if (s < t2) {
        if (s < t1) {
            t2 = t1; i2 = i1;
            if (s < t0) { t1 = t0; i1 = i0; t0 = s; i0 = m; }
            else        { t1 = s;  i1 = m; }
        } else { t2 = s; i2 = m; }
    }
}

// ---------------------------------------------------------------------------
// Kernel 2: fused pairwise-dot GEMM + top-3 + gather/blend.
// Grid: (N_/TILE, B_). Block: 256 threads -> 16x16 thread grid, 8x8 microtile.
// ---------------------------------------------------------------------------
__global__ __launch_bounds__(NT, 1)
void knn_blend_kernel(const float* __restrict__ X,
                      const float* __restrict__ strength,
                      float* __restrict__ Y) {
    const int b     = blockIdx.y;
    const int qbase = blockIdx.x * TILE;
    const float* Xb  = X + (size_t)b * N_ * D_;
    const float* sqb = g_sq + b * N_;

    extern __shared__ float smem[];
    float* Af  = smem;                    // [D_][ASTR]  query tile, k-major
    float* Bsc = Af + D_ * ASTR;          // [KC][ASTR]  candidate K-chunk
    float* Bsq = Bsc + KC * ASTR;         // [TILE]      candidate sq norms
    int*   sIdx = (int*)(Bsq + TILE);     // [TILE][3]   final neighbor indices

    const int tid = threadIdx.x;
    const int tx  = tid & 15;
    const int ty  = tid >> 4;
    const int r0  = ty * 8;               // query rows  r0..r0+7
    const int c0  = tx * 8;               // cand  cols  c0..c0+7

    // --- Load full query tile into shared, transposed to k-major ---
    const float4* X4 = reinterpret_cast<const float4*>(Xb);
    #pragma unroll
    for (int f = tid; f < TILE * (D_ / 4); f += NT) {
        int row = f >> 5;                 // 0..127
        int seg = f & 31;                 // float4 within row
        float4 v = X4[(size_t)(qbase + row) * (D_ / 4) + seg];
        int k = seg * 4;
        Af[(k + 0) * ASTR + row] = v.x;
        Af[(k + 1) * ASTR + row] = v.y;
        Af[(k + 2) * ASTR + row] = v.z;
        Af[(k + 3) * ASTR + row] = v.w;
    }

    // --- per-thread top-3 state (ascending) ---
    float t0[8], t1[8], t2[8];
    int   j0[8], j1[8], j2[8];
    #pragma unroll
    for (int i = 0; i < 8; i++) {
        t0[i] = t1[i] = t2[i] = 3.0e38f;
        j0[i] = j1[i] = j2[i] = 0;
    }

    // B-chunk loader indices: 2 float4 per thread per chunk
    const int f0   = tid * 2;
    const int rowB = f0 >> 2;             // 0..127
    const int seg0 = f0 & 3;              // in {0,2}
    const int seg1 = seg0 + 1;

    // --- loop over candidate tiles ---
    for (int mt = 0; mt < N_ / TILE; mt++) {
        const int mbase = mt * TILE;

        __syncthreads();  // protect Bsq/Bsc reuse vs previous iteration readers
        if (tid < TILE) Bsq[tid] = sqb[mbase + tid];

        float acc[8][8];
        #pragma unroll
        for (int i = 0; i < 8; i++)
            #pragma unroll
            for (int j = 0; j < 8; j++) acc[i][j] = 0.f;

        // prefetch chunk 0
        float4 p0 = X4[(size_t)(mbase + rowB) * (D_ / 4) + 0 * 4 + seg0];
        float4 p1 = X4[(size_t)(mbase + rowB) * (D_ / 4) + 0 * 4 + seg1];

        #pragma unroll
        for (int c = 0; c < D_ / KC; c++) {
            __syncthreads();
            {
                int k0 = seg0 * 4, k1 = seg1 * 4;
                Bsc[(k0 + 0) * ASTR + rowB] = p0.x;
                Bsc[(k0 + 1) * ASTR + rowB] = p0.y;
                Bsc[(k0 + 2) * ASTR + rowB] = p0.z;
                Bsc[(k0 + 3) * ASTR + rowB] = p0.w;
                Bsc[(k1 + 0) * ASTR + rowB] = p1.x;
                Bsc[(k1 + 1) * ASTR + rowB] = p1.y;
                Bsc[(k1 + 2) * ASTR + rowB] = p1.z;
                Bsc[(k1 + 3) * ASTR + rowB] = p1.w;
            }
            __syncthreads();
            if (c < D_ / KC - 1) {
                p0 = X4[(size_t)(mbase + rowB) * (D_ / 4) + (c + 1) * 4 + seg0];
                p1 = X4[(size_t)(mbase + rowB) * (D_ / 4) + (c + 1) * 4 + seg1];
            }
            #pragma unroll
            for (int kk = 0; kk < KC; kk++) {
                const float* arow = Af + (c * KC + kk) * ASTR + r0;
                const float* brow = Bsc + kk * ASTR + c0;
                float4 av0 = *reinterpret_cast<const float4*>(arow);
                float4 av1 = *reinterpret_cast<const float4*>(arow + 4);
                float4 bv0 = *reinterpret_cast<const float4*>(brow);
                float4 bv1 = *reinterpret_cast<const float4*>(brow + 4);
                float a[8] = {av0.x, av0.y, av0.z, av0.w, av1.x, av1.y, av1.z, av1.w};
                float bb[8] = {bv0.x, bv0.y, bv0.z, bv0.w, bv1.x, bv1.y, bv1.z, bv1.w};
                #pragma unroll
                for (int i = 0; i < 8; i++)
                    #pragma unroll
                    for (int j = 0; j < 8; j++)
                        acc[i][j] = fmaf(a[i], bb[j], acc[i][j]);
            }
        }

        // --- score + top-3 update (rank by sq[m] - 2*dot; sq[n] constant/row) ---
        #pragma unroll
        for (int j = 0; j < 8; j++) {
            int   m  = mbase + c0 + j;
            float sm = Bsq[c0 + j];
            #pragma unroll
            for (int i = 0; i < 8; i++) {
                int n = qbase + r0 + i;
                float sc = fmaf(-2.f, acc[i][j], sm);
                if (m != n)
                    ins3(sc, m, t0[i], t1[i], t2[i], j0[i], j1[i], j2[i]);
            }
        }
    }

    // --- merge top-3 across the 16 column-threads of each row ---
    // Row-sharers are lanes {0..15} or {16..31} of one warp -> xor-butterfly.
    #pragma unroll
    for (int off = 8; off >= 1; off >>= 1) {
        #pragma unroll
        for (int i = 0; i < 8; i++) {
            float a0 = __shfl_xor_sync(0xffffffffu, t0[i], off);
            int   b0 = __shfl_xor_sync(0xffffffffu, j0[i], off);
            float a1 = __shfl_xor_sync(0xffffffffu, t1[i], off);
            int   b1 = __shfl_xor_sync(0xffffffffu, j1[i], off);
            float a2 = __shfl_xor_sync(0xffffffffu, t2[i], off);
            int   b2 = __shfl_xor_sync(0xffffffffu, j2[i], off);
            ins3(a0, b0, t0[i], t1[i], t2[i], j0[i], j1[i], j2[i]);
            ins3(a1, b1, t0[i], t1[i], t2[i], j0[i], j1[i], j2[i]);
            ins3(a2, b2, t0[i], t1[i], t2[i], j0[i], j1[i], j2[i]);
        }
    }
    if (tx == 0) {
        #pragma unroll
        for (int i = 0; i < 8; i++) {
            int row = r0 + i;
            sIdx[row * 3 + 0] = j0[i];
            sIdx[row * 3 + 1] = j1[i];
            sIdx[row * 3 + 2] = j2[i];
        }
    }
    __syncthreads();

    // --- gather + blend epilogue: (1-s)*x + (s/3)*(xa+xb+xc) ---
    float s  = fminf(fmaxf(strength[0], 0.f), 1.f);
    float w1 = 1.f - s;
    float w2 = s * (1.f / 3.f);
    int warp = tid >> 5, lane = tid & 31;
    float* Yb = Y + (size_t)b * N_ * D_;
    for (int r = warp; r < TILE; r += NT / 32) {
        int n  = qbase + r;
        int ia = sIdx[r * 3 + 0];
        int ib = sIdx[r * 3 + 1];
        int ic = sIdx[r * 3 + 2];
        float4 vn = X4[(size_t)n  * (D_ / 4) + lane];
        float4 va = X4[(size_t)ia * (D_ / 4) + lane];
        float4 vb = X4[(size_t)ib * (D_ / 4) + lane];
        float4 vc = X4[(size_t)ic * (D_ / 4) + lane];
        float4 o;
        o.x = w1 * vn.x + w2 * (va.x + vb.x + vc.x);
        o.y = w1 * vn.y + w2 * (va.y + vb.y + vc.y);
        o.z = w1 * vn.z + w2 * (va.z + vb.z + vc.z);
        o.w = w1 * vn.w + w2 * (va.w + vb.w + vc.w);
        reinterpret_cast<float4*>(Yb + (size_t)n * D_)[lane] = o;
    }
}

// ---------------------------------------------------------------------------
extern "C" void kernel_launch(void* const* d_in, const int* in_sizes, int n_in,
                              void* d_out, int out_size) {
    const float* X;
    const float* st;
    if (n_in >= 2 && in_sizes[0] == 1) { st = (const float*)d_in[0]; X = (const float*)d_in[1]; }
    else                               { X = (const float*)d_in[0]; st = (const float*)d_in[1]; }
    float* Y = (float*)d_out;

    // squared norms: one warp per point
    int rows = B_ * N_;
    int sq_blocks = (rows * 32 + NT - 1) / NT;
    sq_kernel<<<sq_blocks, NT>>>(X);

    size_t shmem = (size_t)(D_ * ASTR + KC * ASTR + TILE) * sizeof(float)
                 + (size_t)TILE * 3 * sizeof(int);
    cudaFuncSetAttribute(knn_blend_kernel,
                         cudaFuncAttributeMaxDynamicSharedMemorySize, (int)shmem);
    dim3 grid(N_ / TILE, B_);
    knn_blend_kernel<<<grid, NT, shmem>>>(X, st, Y);
}

// round 2
// speedup vs baseline: 1.4067x; 1.4067x over previous
#include <cuda_runtime.h>

// Problem constants (ParacrineCascade: B=32, N=2048, D=128, K=3)
#define B_   32
#define N_   2048
#define D_   128
#define TILE 128
#define KC   16
#define NT   512
#define ASTR (TILE + 4)   // padded smem row stride (floats)

// Scratch for per-point squared norms (no cudaMalloc allowed)
__device__ float g_sq[B_ * N_];

// ---------------------------------------------------------------------------
// packed f32x2 helpers (Blackwell FFMA2 path)
// ---------------------------------------------------------------------------
__device__ __forceinline__ unsigned long long bcast2(float a) {
    unsigned long long r;
    asm("mov.b64 %0, {%1, %1};" : "=l"(r) : "f"(a));
    return r;
}
__device__ __forceinline__ unsigned long long pack2(float lo, float hi) {
    unsigned long long r;
    asm("mov.b64 %0, {%1, %2};" : "=l"(r) : "f"(lo), "f"(hi));
    return r;
}
__device__ __forceinline__ void fma2(unsigned long long& d,
                                     unsigned long long a,
                                     unsigned long long b) {
    asm("fma.rn.f32x2 %0, %1, %2, %0;" : "+l"(d) : "l"(a), "l"(b));
}
__device__ __forceinline__ float2 unpack2(unsigned long long v) {
    float2 f;
    asm("mov.b64 {%0, %1}, %2;" : "=f"(f.x), "=f"(f.y) : "l"(v));
    return f;
}

// ---------------------------------------------------------------------------
// Kernel 1: per-row squared norm, one warp per point.
// ---------------------------------------------------------------------------
__global__ void sq_kernel(const float* __restrict__ X) {
    int gw   = (blockIdx.x * blockDim.x + threadIdx.x) >> 5;
    int lane = threadIdx.x & 31;
    if (gw >= B_ * N_) return;
    const float4* x4 = reinterpret_cast<const float4*>(X) + (size_t)gw * (D_ / 4);
    float4 v = x4[lane];
    float s = v.x * v.x + v.y * v.y + v.z * v.z + v.w * v.w;
    #pragma unroll
    for (int off = 16; off; off >>= 1) s += __shfl_xor_sync(0xffffffffu, s, off);
    if (lane == 0) g_sq[gw] = s;
}

// Insert (s, m) into a sorted ascending top-3 list.
__device__ __forceinline__ void ins3(float s, int m,
                                     float& t0, float& t1, float& t2,
                                     int& i0, int& i1, int& i2) {
    if (s < t2) {
        if (s < t1) {
            t2 = t1; i2 = i1;
            if (s < t0) { t1 = t0; i1 = i0; t0 = s; i0 = m; }
            else        { t1 = s;  i1 = m; }
        } else { t2 = s; i2 = m; }
    }
}

// ---------------------------------------------------------------------------
// Kernel 2: fused pairwise-dot GEMM (f32x2 FFMA2) + top-3 + gather/blend.
// Grid: (N_/TILE, B_). Block: 512 threads -> 32x16 thread grid, 4x8 microtile.
// ---------------------------------------------------------------------------
__global__ __launch_bounds__(NT, 1)
void knn_blend_kernel(const float* __restrict__ X,
                      const float* __restrict__ strength,
                      float* __restrict__ Y) {
    const int b     = blockIdx.y;
    const int qbase = blockIdx.x * TILE;
    const float* Xb  = X + (size_t)b * N_ * D_;
    const float* sqb = g_sq + b * N_;

    extern __shared__ float smem[];
    float* Af  = smem;                    // [D_][ASTR]  query tile, k-major
    float* Bsc = Af + D_ * ASTR;          // [KC][ASTR]  candidate K-chunk
    float* Bsq = Bsc + KC * ASTR;         // [TILE]      candidate sq norms
    int*   sIdx = (int*)(Bsq + TILE);     // [TILE][3]   final neighbor indices

    const int tid = threadIdx.x;
    const int tx  = tid & 15;             // 16 column-thread groups
    const int ty  = tid >> 4;             // 32 row-thread groups
    const int r0  = ty * 4;               // query rows  r0..r0+3
    const int c0  = tx * 8;               // cand  cols  c0..c0+7

    // --- Load full query tile into shared, transposed to k-major ---
    const float4* X4 = reinterpret_cast<const float4*>(Xb);
    #pragma unroll
    for (int f = tid; f < TILE * (D_ / 4); f += NT) {
        int row = f >> 5;                 // 0..127
        int seg = f & 31;                 // float4 within row
        float4 v = X4[(size_t)(qbase + row) * (D_ / 4) + seg];
        int k = seg * 4;
        Af[(k + 0) * ASTR + row] = v.x;
        Af[(k + 1) * ASTR + row] = v.y;
        Af[(k + 2) * ASTR + row] = v.z;
        Af[(k + 3) * ASTR + row] = v.w;
    }

    // --- per-thread top-3 state (ascending), 4 rows ---
    float t0[4], t1[4], t2[4];
    int   j0[4], j1[4], j2[4];
    #pragma unroll
    for (int i = 0; i < 4; i++) {
        t0[i] = t1[i] = t2[i] = 3.0e38f;
        j0[i] = j1[i] = j2[i] = 0;
    }

    // B-chunk loader: 1 float4 per thread per chunk
    const int rowB = tid >> 2;            // 0..127
    const int segB = tid & 3;             // float4 index within KC=16 chunk

    // --- loop over candidate tiles ---
    for (int mt = 0; mt < N_ / TILE; mt++) {
        const int mbase = mt * TILE;

        __syncthreads();  // protect Bsq/Bsc reuse vs previous iteration readers
        if (tid < TILE) Bsq[tid] = sqb[mbase + tid];

        unsigned long long acc[4][4];
        #pragma unroll
        for (int i = 0; i < 4; i++)
            #pragma unroll
            for (int j = 0; j < 4; j++) acc[i][j] = 0ull;

        // prefetch chunk 0
        float4 p0 = X4[(size_t)(mbase + rowB) * (D_ / 4) + segB];

        #pragma unroll
        for (int c = 0; c < D_ / KC; c++) {
            __syncthreads();
            {
                int k0 = segB * 4;
                Bsc[(k0 + 0) * ASTR + rowB] = p0.x;
                Bsc[(k0 + 1) * ASTR + rowB] = p0.y;
                Bsc[(k0 + 2) * ASTR + rowB] = p0.z;
                Bsc[(k0 + 3) * ASTR + rowB] = p0.w;
            }
            __syncthreads();
            if (c < D_ / KC - 1) {
                p0 = X4[(size_t)(mbase + rowB) * (D_ / 4) + (c + 1) * 4 + segB];
            }
            #pragma unroll
            for (int kk = 0; kk < KC; kk++) {
                const float* arow = Af + (c * KC + kk) * ASTR + r0;
                const float* brow = Bsc + kk * ASTR + c0;
                float4 av  = *reinterpret_cast<const float4*>(arow);
                float4 bv0 = *reinterpret_cast<const float4*>(brow);
                float4 bv1 = *reinterpret_cast<const float4*>(brow + 4);
                unsigned long long a2[4], b2[4];
                a2[0] = bcast2(av.x); a2[1] = bcast2(av.y);
                a2[2] = bcast2(av.z); a2[3] = bcast2(av.w);
                b2[0] = pack2(bv0.x, bv0.y); b2[1] = pack2(bv0.z, bv0.w);
                b2[2] = pack2(bv1.x, bv1.y); b2[3] = pack2(bv1.z, bv1.w);
                #pragma unroll
                for (int i = 0; i < 4; i++)
                    #pragma unroll
                    for (int j = 0; j < 4; j++)
                        fma2(acc[i][j], a2[i], b2[j]);
            }
        }

        // --- score + top-3 update (rank by sq[m] - 2*dot; sq[n] constant/row) ---
        #pragma unroll
        for (int jj = 0; jj < 4; jj++) {
            int   m0  = mbase + c0 + 2 * jj;
            float sm0 = Bsq[c0 + 2 * jj];
            float sm1 = Bsq[c0 + 2 * jj + 1];
            #pragma unroll
            for (int i = 0; i < 4; i++) {
                int n = qbase + r0 + i;
                float2 d = unpack2(acc[i][jj]);
                float sc0 = fmaf(-2.f, d.x, sm0);
                float sc1 = fmaf(-2.f, d.y, sm1);
                if (m0 != n)
                    ins3(sc0, m0, t0[i], t1[i], t2[i], j0[i], j1[i], j2[i]);
                if (m0 + 1 != n)
                    ins3(sc1, m0 + 1, t0[i], t1[i], t2[i], j0[i], j1[i], j2[i]);
            }
        }
    }

    // --- merge top-3 across the 16 column-threads of each row ---
    // Row-sharers are lanes {0..15} or {16..31} of one warp -> xor-butterfly.
    #pragma unroll
    for (int off = 8; off >= 1; off >>= 1) {
        #pragma unroll
        for (int i = 0; i < 4; i++) {
            float a0 = __shfl_xor_sync(0xffffffffu, t0[i], off);
            int   b0 = __shfl_xor_sync(0xffffffffu, j0[i], off);
            float a1 = __shfl_xor_sync(0xffffffffu, t1[i], off);
            int   b1 = __shfl_xor_sync(0xffffffffu, j1[i], off);
            float a2 = __shfl_xor_sync(0xffffffffu, t2[i], off);
            int   b2 = __shfl_xor_sync(0xffffffffu, j2[i], off);
            ins3(a0, b0, t0[i], t1[i], t2[i], j0[i], j1[i], j2[i]);
            ins3(a1, b1, t0[i], t1[i], t2[i], j0[i], j1[i], j2[i]);
            ins3(a2, b2, t0[i], t1[i], t2[i], j0[i], j1[i], j2[i]);
        }
    }
    if (tx == 0) {
        #pragma unroll
        for (int i = 0; i < 4; i++) {
            int row = r0 + i;
            sIdx[row * 3 + 0] = j0[i];
            sIdx[row * 3 + 1] = j1[i];
            sIdx[row * 3 + 2] = j2[i];
        }
    }
    __syncthreads();

    // --- gather + blend epilogue: (1-s)*x + (s/3)*(xa+xb+xc) ---
    float s  = fminf(fmaxf(strength[0], 0.f), 1.f);
    float w1 = 1.f - s;
    float w2 = s * (1.f / 3.f);
    int warp = tid >> 5, lane = tid & 31;
    float* Yb = Y + (size_t)b * N_ * D_;
    for (int r = warp; r < TILE; r += NT / 32) {
        int n  = qbase + r;
        int ia = sIdx[r * 3 + 0];
        int ib = sIdx[r * 3 + 1];
        int ic = sIdx[r * 3 + 2];
        float4 vn = X4[(size_t)n  * (D_ / 4) + lane];
        float4 va = X4[(size_t)ia * (D_ / 4) + lane];
        float4 vb = X4[(size_t)ib * (D_ / 4) + lane];
        float4 vc = X4[(size_t)ic * (D_ / 4) + lane];
        float4 o;
        o.x = w1 * vn.x + w2 * (va.x + vb.x + vc.x);
        o.y = w1 * vn.y + w2 * (va.y + vb.y + vc.y);
        o.z = w1 * vn.z + w2 * (va.z + vb.z + vc.z);
        o.w = w1 * vn.w + w2 * (va.w + vb.w + vc.w);
        reinterpret_cast<float4*>(Yb + (size_t)n * D_)[lane] = o;
    }
}

// ---------------------------------------------------------------------------
extern "C" void kernel_launch(void* const* d_in, const int* in_sizes, int n_in,
                              void* d_out, int out_size) {
    const float* X;
    const float* st;
    if (n_in >= 2 && in_sizes[0] == 1) { st = (const float*)d_in[0]; X = (const float*)d_in[1]; }
    else                               { X = (const float*)d_in[0]; st = (const float*)d_in[1]; }
    float* Y = (float*)d_out;

    // squared norms: one warp per point
    int rows = B_ * N_;
    int sq_blocks = (rows * 32 + 255) / 256;
    sq_kernel<<<sq_blocks, 256>>>(X);

    size_t shmem = (size_t)(D_ * ASTR + KC * ASTR + TILE) * sizeof(float)
                 + (size_t)TILE * 3 * sizeof(int);
    cudaFuncSetAttribute(knn_blend_kernel,
                         cudaFuncAttributeMaxDynamicSharedMemorySize, (int)shmem);
    dim3 grid(N_ / TILE, B_);
    knn_blend_kernel<<<grid, NT, shmem>>>(X, st, Y);
}

// round 3
// speedup vs baseline: 1.8443x; 1.3111x over previous
#include <cuda_runtime.h>

// Problem constants (ParacrineCascade: B=32, N=2048, D=128, K=3)
#define B_     32
#define N_     2048
#define D_     128
#define NROWS  128            // query rows per CTA
#define NCOLS  256            // candidate cols per tile
#define KC     16             // k-chunk depth
#define NT     512
#define ASTR   132            // Af row stride (floats), 528B (16B-aligned)
#define BSTR   260            // Bsc row stride (floats), 1040B (16B-aligned)
#define KCCH   (KC * BSTR)    // one Bsc buffer, in floats

// Scratch for per-point squared norms (no cudaMalloc allowed)
__device__ float g_sq[B_ * N_];

typedef unsigned long long ull;

__device__ __forceinline__ ull bcast2(float a) {
    ull r; asm("mov.b64 %0, {%1, %1};" : "=l"(r) : "f"(a)); return r;
}
__device__ __forceinline__ void fma2(ull& d, ull a, ull b) {
    asm("fma.rn.f32x2 %0, %1, %2, %0;" : "+l"(d) : "l"(a), "l"(b));
}
__device__ __forceinline__ float2 unpack2(ull v) {
    float2 f; asm("mov.b64 {%0, %1}, %2;" : "=f"(f.x), "=f"(f.y) : "l"(v)); return f;
}

// ---------------------------------------------------------------------------
__global__ void sq_kernel(const float* __restrict__ X) {
    int gw   = (blockIdx.x * blockDim.x + threadIdx.x) >> 5;
    int lane = threadIdx.x & 31;
    if (gw >= B_ * N_) return;
    const float4* x4 = reinterpret_cast<const float4*>(X) + (size_t)gw * (D_ / 4);
    float4 v = x4[lane];
    float s = v.x * v.x + v.y * v.y + v.z * v.z + v.w * v.w;
    #pragma unroll
    for (int off = 16; off; off >>= 1) s += __shfl_xor_sync(0xffffffffu, s, off);
    if (lane == 0) g_sq[gw] = s;
}

__device__ __forceinline__ void ins3(float s, int m,
                                     float& t0, float& t1, float& t2,
                                     int& i0, int& i1, int& i2) {
    if (s < t2) {
        if (s < t1) {
            t2 = t1; i2 = i1;
            if (s < t0) { t1 = t0; i1 = i0; t0 = s; i0 = m; }
            else        { t1 = s;  i1 = m; }
        } else { t2 = s; i2 = m; }
    }
}

// ---------------------------------------------------------------------------
// Fused pairwise-dot GEMM (FFMA2) + top-3 + gather/blend.
// Grid (N_/NROWS, B_). 512 threads: ty=tid>>5 (16 row groups, 1 per warp),
// tx=lane (32 col groups). Microtile 8x8. Tile 128x256.
// A loads are warp-uniform broadcasts -> crossbar cost is B-side only.
// ---------------------------------------------------------------------------
__global__ __launch_bounds__(NT, 1)
void knn_blend_kernel(const float* __restrict__ X,
                      const float* __restrict__ strength,
                      float* __restrict__ Y) {
    const int b     = blockIdx.y;
    const int qbase = blockIdx.x * NROWS;
    const float* Xb  = X + (size_t)b * N_ * D_;
    const float* sqb = g_sq + b * N_;

    extern __shared__ float smem[];
    float* Af  = smem;                       // [D_][ASTR]
    float* Bsc = Af + D_ * ASTR;             // [2][KC][BSTR]
    int* sIdx  = (int*)(Bsc + 2 * KCCH);     // [NROWS][3]

    const int tid  = threadIdx.x;
    const int lane = tid & 31;
    const int ty   = tid >> 5;               // warp id = row group
    const int r0   = ty * 8;
    const int c0   = lane * 8;

    const float4* X4 = reinterpret_cast<const float4*>(Xb);

    // --- Load query tile (128 rows x 128 k), transposed to k-major ---
    #pragma unroll
    for (int it = 0; it < (NROWS * (D_ / 4)) / NT; it++) {
        int f   = tid + it * NT;
        int row = f >> 5;
        int seg = f & 31;
        float4 v = X4[(size_t)(qbase + row) * (D_ / 4) + seg];
        int k = seg * 4;
        Af[(k + 0) * ASTR + row] = v.x;
        Af[(k + 1) * ASTR + row] = v.y;
        Af[(k + 2) * ASTR + row] = v.z;
        Af[(k + 3) * ASTR + row] = v.w;
    }

    // --- top-3 state, 8 rows per thread ---
    float t0[8], t1[8], t2[8];
    int   j0[8], j1[8], j2[8];
    #pragma unroll
    for (int i = 0; i < 8; i++) {
        t0[i] = t1[i] = t2[i] = 3.0e38f;
        j0[i] = j1[i] = j2[i] = 0;
    }

    // B chunk loader: 2 float4 per thread per chunk (1024 slots / 512 thr)
    // slot s: m = s & 255, kseg = s >> 8
    const int mA = tid & 255, ksegA = tid >> 8;          // slots tid
    const int mB = mA,        ksegB = ksegA + 2;         // slots tid+512

    const int NMT = N_ / NCOLS;       // 8 col tiles
    const int NCH = D_ / KC;          // 8 chunks per tile

    // prefetch global chunk 0
    float4 pA = X4[(size_t)mA * (D_ / 4) + ksegA];
    float4 pB = X4[(size_t)mB * (D_ / 4) + ksegB];
    __syncthreads();                  // Af ready
    {
        int kA = ksegA * 4, kB = ksegB * 4;
        Bsc[(kA + 0) * BSTR + mA] = pA.x; Bsc[(kA + 1) * BSTR + mA] = pA.y;
        Bsc[(kA + 2) * BSTR + mA] = pA.z; Bsc[(kA + 3) * BSTR + mA] = pA.w;
        Bsc[(kB + 0) * BSTR + mB] = pB.x; Bsc[(kB + 1) * BSTR + mB] = pB.y;
        Bsc[(kB + 2) * BSTR + mB] = pB.z; Bsc[(kB + 3) * BSTR + mB] = pB.w;
    }
    __syncthreads();

    for (int mt = 0; mt < NMT; mt++) {
        const int mbase = mt * NCOLS;

        ull acc[8][4];
        #pragma unroll
        for (int i = 0; i < 8; i++)
            #pragma unroll
            for (int j = 0; j < 4; j++) acc[i][j] = 0ull;

        #pragma unroll
        for (int c = 0; c < NCH; c++) {
            const int gc   = mt * NCH + c;           // global chunk idx
            const bool last = (gc == NMT * NCH - 1);
            const float* Bcur = Bsc + (gc & 1) * KCCH;

            // prefetch next chunk to registers
            if (!last) {
                int gn = gc + 1;
                int nmb = (gn >> 3) * NCOLS;
                int nc  = gn & 7;
                pA = X4[(size_t)(nmb + mA) * (D_ / 4) + nc * 4 + ksegA];
                pB = X4[(size_t)(nmb + mB) * (D_ / 4) + nc * 4 + ksegB];
            }

            // compute this chunk
            #pragma unroll
            for (int kk = 0; kk < KC; kk++) {
                const float* arow = Af + (c * KC + kk) * ASTR + r0;
                float4 av0 = *reinterpret_cast<const float4*>(arow);      // bcast
                float4 av1 = *reinterpret_cast<const float4*>(arow + 4);  // bcast
                const ulonglong2* brow =
                    reinterpret_cast<const ulonglong2*>(Bcur + kk * BSTR + c0);
                ulonglong2 bq0 = brow[0];
                ulonglong2 bq1 = brow[1];
                ull bb[4] = {bq0.x, bq0.y, bq1.x, bq1.y};
                ull a2[8];
                a2[0] = bcast2(av0.x); a2[1] = bcast2(av0.y);
                a2[2] = bcast2(av0.z); a2[3] = bcast2(av0.w);
                a2[4] = bcast2(av1.x); a2[5] = bcast2(av1.y);
                a2[6] = bcast2(av1.z); a2[7] = bcast2(av1.w);
                #pragma unroll
                for (int i = 0; i < 8; i++)
                    #pragma unroll
                    for (int j = 0; j < 4; j++)
                        fma2(acc[i][j], a2[i], bb[j]);
            }

            // publish next chunk
            if (!last) {
                float* Bnxt = Bsc + ((gc + 1) & 1) * KCCH;
                int kA = ksegA * 4, kB = ksegB * 4;
                Bnxt[(kA + 0) * BSTR + mA] = pA.x; Bnxt[(kA + 1) * BSTR + mA] = pA.y;
                Bnxt[(kA + 2) * BSTR + mA] = pA.z; Bnxt[(kA + 3) * BSTR + mA] = pA.w;
                Bnxt[(kB + 0) * BSTR + mB] = pB.x; Bnxt[(kB + 1) * BSTR + mB] = pB.y;
                Bnxt[(kB + 2) * BSTR + mB] = pB.z; Bnxt[(kB + 3) * BSTR + mB] = pB.w;
                __syncthreads();
            }
        }

        // --- score + top-3 (rank by sq[m] - 2*dot) ---
        #pragma unroll
        for (int jj = 0; jj < 4; jj++) {
            int   m0  = mbase + c0 + 2 * jj;
            float sm0 = __ldg(sqb + m0);
            float sm1 = __ldg(sqb + m0 + 1);
            #pragma unroll
            for (int i = 0; i < 8; i++) {
                int n = qbase + r0 + i;
                float2 d = unpack2(acc[i][jj]);
                float sc0 = fmaf(-2.f, d.x, sm0);
                float sc1 = fmaf(-2.f, d.y, sm1);
                if (m0 != n)
                    ins3(sc0, m0, t0[i], t1[i], t2[i], j0[i], j1[i], j2[i]);
                if (m0 + 1 != n)
                    ins3(sc1, m0 + 1, t0[i], t1[i], t2[i], j0[i], j1[i], j2[i]);
            }
        }
    }

    // --- merge top-3 across the 32 lanes (one warp = one row group) ---
    #pragma unroll
    for (int off = 16; off >= 1; off >>= 1) {
        #pragma unroll
        for (int i = 0; i < 8; i++) {
            float a0 = __shfl_xor_sync(0xffffffffu, t0[i], off);
            int   b0 = __shfl_xor_sync(0xffffffffu, j0[i], off);
            float a1 = __shfl_xor_sync(0xffffffffu, t1[i], off);
            int   b1 = __shfl_xor_sync(0xffffffffu, j1[i], off);
            float a2 = __shfl_xor_sync(0xffffffffu, t2[i], off);
            int   b2 = __shfl_xor_sync(0xffffffffu, j2[i], off);
            ins3(a0, b0, t0[i], t1[i], t2[i], j0[i], j1[i], j2[i]);
            ins3(a1, b1, t0[i], t1[i], t2[i], j0[i], j1[i], j2[i]);
            ins3(a2, b2, t0[i], t1[i], t2[i], j0[i], j1[i], j2[i]);
        }
    }
    if (lane == 0) {
        #pragma unroll
        for (int i = 0; i < 8; i++) {
            int row = r0 + i;
            sIdx[row * 3 + 0] = j0[i];
            sIdx[row * 3 + 1] = j1[i];
            sIdx[row * 3 + 2] = j2[i];
        }
    }
    __syncthreads();

    // --- gather + blend: (1-s)*x + (s/3)*(xa+xb+xc) ---
    float s  = fminf(fmaxf(strength[0], 0.f), 1.f);
    float w1 = 1.f - s;
    float w2 = s * (1.f / 3.f);
    float* Yb = Y + (size_t)b * N_ * D_;
    for (int r = ty; r < NROWS; r += NT / 32) {
        int n  = qbase + r;
        int ia = sIdx[r * 3 + 0];
        int ib = sIdx[r * 3 + 1];
        int ic = sIdx[r * 3 + 2];
        float4 vn = X4[(size_t)n  * (D_ / 4) + lane];
        float4 va = X4[(size_t)ia * (D_ / 4) + lane];
        float4 vb = X4[(size_t)ib * (D_ / 4) + lane];
        float4 vc = X4[(size_t)ic * (D_ / 4) + lane];
        float4 o;
        o.x = w1 * vn.x + w2 * (va.x + vb.x + vc.x);
        o.y = w1 * vn.y + w2 * (va.y + vb.y + vc.y);
        o.z = w1 * vn.z + w2 * (va.z + vb.z + vc.z);
        o.w = w1 * vn.w + w2 * (va.w + vb.w + vc.w);
        reinterpret_cast<float4*>(Yb + (size_t)n * D_)[lane] = o;
    }
}

// ---------------------------------------------------------------------------
extern "C" void kernel_launch(void* const* d_in, const int* in_sizes, int n_in,
                              void* d_out, int out_size) {
    const float* X;
    const float* st;
    if (n_in >= 2 && in_sizes[0] == 1) { st = (const float*)d_in[0]; X = (const float*)d_in[1]; }
    else                               { X = (const float*)d_in[0]; st = (const float*)d_in[1]; }
    float* Y = (float*)d_out;

    int rows = B_ * N_;
    int sq_blocks = (rows * 32 + 255) / 256;
    sq_kernel<<<sq_blocks, 256>>>(X);

    size_t shmem = (size_t)(D_ * ASTR + 2 * KCCH) * sizeof(float)
                 + (size_t)NROWS * 3 * sizeof(int);
    cudaFuncSetAttribute(knn_blend_kernel,
                         cudaFuncAttributeMaxDynamicSharedMemorySize, (int)shmem);
    dim3 grid(N_ / NROWS, B_);
    knn_blend_kernel<<<grid, NT, shmem>>>(X, st, Y);
}

// round 5
// speedup vs baseline: 2.3906x; 1.2962x over previous
#include <cuda_runtime.h>
#include <cuda_fp16.h>
#include <cstdint>

// Problem constants (ParacrineCascade: B=32, N=2048, D=128, K=3)
#define B_     32
#define N_     2048
#define D_     128
#define QT     128                // queries per CTA
#define CT     128                // candidates per tile
#define NTILE  (N_ / CT)          // 16
#define NT     512                // threads

// smem byte offsets
#define OFF_A    0                // 64KB  query tile (K=256 fp16, swizzled)
#define OFF_B    65536            // 64KB  candidate tile
#define OFF_S    131072           // score tile 128 x 132 f32
#define SSTR     132
#define OFF_BSQ  198656           // [2][128] f32
#define OFF_SIDX 199680           // [128][3] int
#define SMEM_TOTAL 201216

// device scratch (no cudaMalloc allowed)
__device__ float              g_sq [B_ * N_];
__device__ unsigned long long g_ext[(size_t)B_ * N_ * 64];  // [row][64] u64: hi(32) | lo(32)

typedef unsigned long long u64;

__device__ __forceinline__ uint32_t smem_u32(const void* p) {
    uint32_t a;
    asm("{ .reg .u64 t; cvta.to.shared.u64 t, %1; cvt.u32.u64 %0, t; }"
        : "=r"(a) : "l"(p));
    return a;
}

__device__ __forceinline__ void ldsm4(uint32_t& r0, uint32_t& r1,
                                      uint32_t& r2, uint32_t& r3, uint32_t addr) {
    asm volatile("ldmatrix.sync.aligned.m8n8.x4.shared.b16 {%0,%1,%2,%3}, [%4];"
                 : "=r"(r0), "=r"(r1), "=r"(r2), "=r"(r3) : "r"(addr));
}

__device__ __forceinline__ void mma16816(float& d0, float& d1, float& d2, float& d3,
                                         uint32_t a0, uint32_t a1, uint32_t a2, uint32_t a3,
                                         uint32_t b0, uint32_t b1) {
    asm volatile("mma.sync.aligned.m16n8k16.row.col.f32.f16.f16.f32 "
                 "{%0,%1,%2,%3}, {%4,%5,%6,%7}, {%8,%9}, {%0,%1,%2,%3};"
                 : "+f"(d0), "+f"(d1), "+f"(d2), "+f"(d3)
                 : "r"(a0), "r"(a1), "r"(a2), "r"(a3), "r"(b0), "r"(b1));
}

// ---------------------------------------------------------------------------
// prep: squared norms (fp32) + fp16 hi/lo split -> g_ext. one warp per point.
// ---------------------------------------------------------------------------
__global__ void prep_kernel(const float* __restrict__ X) {
    int row  = (blockIdx.x * blockDim.x + threadIdx.x) >> 5;
    int lane = threadIdx.x & 31;
    if (row >= B_ * N_) return;
    float4 v = reinterpret_cast<const float4*>(X)[(size_t)row * 32 + lane];
    float s = v.x * v.x + v.y * v.y + v.z * v.z + v.w * v.w;
    #pragma unroll
    for (int off = 16; off; off >>= 1) s += __shfl_xor_sync(0xffffffffu, s, off);
    if (lane == 0) g_sq[row] = s;

    __half h0 = __float2half_rn(v.x), h1 = __float2half_rn(v.y);
    __half h2 = __float2half_rn(v.z), h3 = __float2half_rn(v.w);
    __half l0 = __float2half_rn(v.x - __half2float(h0));
    __half l1 = __float2half_rn(v.y - __half2float(h1));
    __half l2 = __float2half_rn(v.z - __half2float(h2));
    __half l3 = __float2half_rn(v.w - __half2float(h3));
    u64 hp = (u64)__half_as_ushort(h0)        | ((u64)__half_as_ushort(h1) << 16)
           | ((u64)__half_as_ushort(h2) << 32) | ((u64)__half_as_ushort(h3) << 48);
    u64 lp = (u64)__half_as_ushort(l0)        | ((u64)__half_as_ushort(l1) << 16)
           | ((u64)__half_as_ushort(l2) << 32) | ((u64)__half_as_ushort(l3) << 48);
    g_ext[(size_t)row * 64 + lane]      = hp;   // k 0..127  (hi)
    g_ext[(size_t)row * 64 + 32 + lane] = lp;   // k 128..255 (lo)
}

// ---------------------------------------------------------------------------
// main kernel: mma.sync fp16 3-pass GEMM + fused top-3 + gather/blend
// grid (16, 32), 512 threads. warp grid 4x4, warp tile 32x32.
// ---------------------------------------------------------------------------
__global__ __launch_bounds__(NT, 1)
void knn_mma_kernel(const float* __restrict__ X,
                    const float* __restrict__ strength,
                    float* __restrict__ Y) {
    extern __shared__ char smem[];
    const uint32_t sb = smem_u32(smem);
    const int tid  = threadIdx.x;
    const int wid  = tid >> 5;
    const int lane = tid & 31;
    const int b     = blockIdx.y;
    const int qbase = blockIdx.x * QT;
    const int xbase = b * N_;

    const uint4* E4 = reinterpret_cast<const uint4*>(g_ext);  // [row][32] 16B chunks
    float* Ssm  = (float*)(smem + OFF_S);
    float* Bsq  = (float*)(smem + OFF_BSQ);      // [2][128]
    int*   sIdx = (int*)(smem + OFF_SIDX);

    // ---- load A (query) tile: 4096 chunks, swizzled ----
    #pragma unroll
    for (int i = 0; i < 8; i++) {
        int li  = tid + i * NT;
        int row = li >> 5, cc = li & 31;
        uint4 v = E4[(size_t)(xbase + qbase + row) * 32 + cc];
        *reinterpret_cast<uint4*>(smem + OFF_A + row * 512
                                  + ((cc ^ (row & 7)) << 4)) = v;
    }
    // ---- load B tile 0 ----
    #pragma unroll
    for (int i = 0; i < 8; i++) {
        int li  = tid + i * NT;
        int row = li >> 5, cc = li & 31;
        uint4 v = E4[(size_t)(xbase + row) * 32 + cc];
        *reinterpret_cast<uint4*>(smem + OFF_B + row * 512
                                  + ((cc ^ (row & 7)) << 4)) = v;
    }
    if (tid < CT) Bsq[tid] = g_sq[xbase + tid];
    __syncthreads();

    // warp tile position
    const int m0 = (wid & 3) * 32;
    const int n0 = (wid >> 2) * 32;

    // ldmatrix per-thread row bases
    const int rowA  = (lane & 15);                          // + m0 + mi*16
    const int lcA   = lane >> 4;                            // chunk +0/+1
    const int rowB  = ((lane & 16) >> 1) + (lane & 7);      // + n0 + ni2*16
    const int lcB   = (lane >> 3) & 1;
    const int rc    = lane & 7;

    uint32_t aBase[2], bBase[2];
    #pragma unroll
    for (int mi = 0; mi < 2; mi++)
        aBase[mi] = sb + OFF_A + (m0 + mi * 16 + rowA) * 512;
    #pragma unroll
    for (int ni2 = 0; ni2 < 2; ni2++)
        bBase[ni2] = sb + OFF_B + (n0 + ni2 * 16 + rowB) * 512;

    // top-3 state: one row per 4 threads (persistent across tiles)
    const int r_loc = tid >> 2;
    const int sub   = tid & 3;
    const int nglob = qbase + r_loc;
    float t0 = 3.0e38f, t1 = 3.0e38f, t2 = 3.0e38f;
    int   i0 = 0, i1 = 0, i2 = 0;

    for (int ct = 0; ct < NTILE; ct++) {
        // prefetch next B tile + sq into registers
        uint4 p[8];
        float psq = 0.f;
        if (ct < NTILE - 1) {
            const int nmb = (ct + 1) * CT;
            #pragma unroll
            for (int i = 0; i < 8; i++) {
                int li  = tid + i * NT;
                int row = li >> 5, cc = li & 31;
                p[i] = E4[(size_t)(xbase + nmb + row) * 32 + cc];
            }
            if (tid < CT) psq = g_sq[xbase + nmb + tid];
        }

        // ---- 3-pass MMA over K (24 k16 steps) ----
        float d[2][4][4];
        #pragma unroll
        for (int mi = 0; mi < 2; mi++)
            #pragma unroll
            for (int ni = 0; ni < 4; ni++)
                #pragma unroll
                for (int e = 0; e < 4; e++) d[mi][ni][e] = 0.f;

        #pragma unroll
        for (int pss = 0; pss < 3; pss++) {
            const int ab = (pss == 2) ? 16 : 0;   // A: lo on pass 2
            const int bbc = (pss == 1) ? 16 : 0;  // B: lo on pass 1
            #pragma unroll
            for (int k = 0; k < 8; k++) {
                uint32_t a[2][4], q[2][4];
                #pragma unroll
                for (int mi = 0; mi < 2; mi++) {
                    uint32_t ch = (uint32_t)(ab + 2 * k + lcA);
                    ldsm4(a[mi][0], a[mi][1], a[mi][2], a[mi][3],
                          aBase[mi] + ((ch ^ (uint32_t)rc) << 4));
                }
                #pragma unroll
                for (int ni2 = 0; ni2 < 2; ni2++) {
                    uint32_t ch = (uint32_t)(bbc + 2 * k + lcB);
                    ldsm4(q[ni2][0], q[ni2][1], q[ni2][2], q[ni2][3],
                          bBase[ni2] + ((ch ^ (uint32_t)rc) << 4));
                }
                #pragma unroll
                for (int mi = 0; mi < 2; mi++)
                    #pragma unroll
                    for (int ni = 0; ni < 4; ni++)
                        mma16816(d[mi][ni][0], d[mi][ni][1], d[mi][ni][2], d[mi][ni][3],
                                 a[mi][0], a[mi][1], a[mi][2], a[mi][3],
                                 q[ni >> 1][(ni & 1) * 2], q[ni >> 1][(ni & 1) * 2 + 1]);
            }
        }

        // ---- write scores (dot products) to smem ----
        {
            const int rr = lane >> 2;
            const int cc2 = (lane & 3) * 2;
            #pragma unroll
            for (int mi = 0; mi < 2; mi++)
                #pragma unroll
                for (int ni = 0; ni < 4; ni++) {
                    int row = m0 + mi * 16 + rr;
                    int col = n0 + ni * 8 + cc2;
                    *reinterpret_cast<float2*>(Ssm + row * SSTR + col)
                        = make_float2(d[mi][ni][0], d[mi][ni][1]);
                    *reinterpret_cast<float2*>(Ssm + (row + 8) * SSTR + col)
                        = make_float2(d[mi][ni][2], d[mi][ni][3]);
                }
        }
        __syncthreads();   // scores visible; B fully consumed

        // ---- publish next B tile ----
        if (ct < NTILE - 1) {
            #pragma unroll
            for (int i = 0; i < 8; i++) {
                int li  = tid + i * NT;
                int row = li >> 5, cc = li & 31;
                *reinterpret_cast<uint4*>(smem + OFF_B + row * 512
                                          + ((cc ^ (row & 7)) << 4)) = p[i];
            }
            if (tid < CT) Bsq[((ct + 1) & 1) * CT + tid] = psq;
        }

        // ---- scan scores: 4 threads per row, 32 candidates each ----
        {
            const float* srow = Ssm + r_loc * SSTR + sub * 32;
            const float* sqr  = Bsq + (ct & 1) * CT + sub * 32;
            const int mb = ct * CT + sub * 32;
            #pragma unroll
            for (int j = 0; j < 8; j++) {
                float4 dv = *reinterpret_cast<const float4*>(srow + 4 * j);
                float4 qv = *reinterpret_cast<const float4*>(sqr + 4 * j);
                float sc[4] = { fmaf(-2.f, dv.x, qv.x), fmaf(-2.f, dv.y, qv.y),
                                fmaf(-2.f, dv.z, qv.z), fmaf(-2.f, dv.w, qv.w) };
                #pragma unroll
                for (int e = 0; e < 4; e++) {
                    int m = mb + 4 * j + e;
                    if (sc[e] < t2 && m != nglob) {
                        if (sc[e] < t1) {
                            t2 = t1; i2 = i1;
                            if (sc[e] < t0) { t1 = t0; i1 = i0; t0 = sc[e]; i0 = m; }
                            else            { t1 = sc[e]; i1 = m; }
                        } else { t2 = sc[e]; i2 = m; }
                    }
                }
            }
        }
        __syncthreads();   // scan done; S and B safe to overwrite
    }

    // ---- merge top-3 across the 4 sub-threads of each row (same warp) ----
    #pragma unroll
    for (int off = 1; off <= 2; off <<= 1) {
        float a0 = __shfl_xor_sync(0xffffffffu, t0, off);
        int   b0 = __shfl_xor_sync(0xffffffffu, i0, off);
        float a1 = __shfl_xor_sync(0xffffffffu, t1, off);
        int   b1 = __shfl_xor_sync(0xffffffffu, i1, off);
        float a2 = __shfl_xor_sync(0xffffffffu, t2, off);
        int   b2 = __shfl_xor_sync(0xffffffffu, i2, off);
        float s_[3] = {a0, a1, a2};
        int   m_[3] = {b0, b1, b2};
        #pragma unroll
        for (int e = 0; e < 3; e++) {
            float s = s_[e]; int m = m_[e];
            if (s < t2) {
                if (s < t1) {
                    t2 = t1; i2 = i1;
                    if (s < t0) { t1 = t0; i1 = i0; t0 = s; i0 = m; }
                    else        { t1 = s;  i1 = m; }
                } else { t2 = s; i2 = m; }
            }
        }
    }
    if (sub == 0) {
        sIdx[r_loc * 3 + 0] = i0;
        sIdx[r_loc * 3 + 1] = i1;
        sIdx[r_loc * 3 + 2] = i2;
    }
    __syncthreads();

    // ---- gather + blend: (1-s)*x + (s/3)*(xa+xb+xc), original fp32 data ----
    float s  = fminf(fmaxf(strength[0], 0.f), 1.f);
    float w1 = 1.f - s;
    float w2 = s * (1.f / 3.f);
    const float4* X4 = reinterpret_cast<const float4*>(X + (size_t)b * N_ * D_);
    float* Yb = Y + (size_t)b * N_ * D_;
    for (int r = wid; r < QT; r += NT / 32) {
        int n  = qbase + r;
        int ia = sIdx[r * 3 + 0];
        int ib = sIdx[r * 3 + 1];
        int ic = sIdx[r * 3 + 2];
        float4 vn = X4[(size_t)n  * 32 + lane];
        float4 va = X4[(size_t)ia * 32 + lane];
        float4 vb = X4[(size_t)ib * 32 + lane];
        float4 vc = X4[(size_t)ic * 32 + lane];
        float4 o;
        o.x = w1 * vn.x + w2 * (va.x + vb.x + vc.x);
        o.y = w1 * vn.y + w2 * (va.y + vb.y + vc.y);
        o.z = w1 * vn.z + w2 * (va.z + vb.z + vc.z);
        o.w = w1 * vn.w + w2 * (va.w + vb.w + vc.w);
        reinterpret_cast<float4*>(Yb + (size_t)n * D_)[lane] = o;
    }
}

// ---------------------------------------------------------------------------
extern "C" void kernel_launch(void* const* d_in, const int* in_sizes, int n_in,
                              void* d_out, int out_size) {
    const float* X;
    const float* st;
    if (n_in >= 2 && in_sizes[0] == 1) { st = (const float*)d_in[0]; X = (const float*)d_in[1]; }
    else                               { X = (const float*)d_in[0]; st = (const float*)d_in[1]; }
    float* Y = (float*)d_out;

    int rows = B_ * N_;
    prep_kernel<<<(rows * 32 + 255) / 256, 256>>>(X);

    cudaFuncSetAttribute(knn_mma_kernel,
                         cudaFuncAttributeMaxDynamicSharedMemorySize, SMEM_TOTAL);
    dim3 grid(N_ / QT, B_);
    knn_mma_kernel<<<grid, NT, SMEM_TOTAL>>>(X, st, Y);
}

// round 9
// speedup vs baseline: 2.8312x; 1.1843x over previous
#include <cuda_runtime.h>
#include <cuda_fp16.h>
#include <cstdint>

// Problem constants (ParacrineCascade: B=32, N=2048, D=128, K=3)
#define B_     32
#define N_     2048
#define D_     128
#define QT     128                // queries per CTA
#define CT     128                // candidates per tile
#define NTILE  (N_ / CT)          // 16
#define NT     512                // threads

// smem byte offsets
#define OFF_A    0                // 64KB  query tile (K=256 fp16, swizzled)
#define OFF_B    65536            // 2 x 64KB candidate tiles
#define OFF_MRGV 196608           // 128*4*3 f32 = 6KB
#define OFF_MRGI 202752           // 128*4*3 int = 6KB
#define OFF_SIDX 208896           // 128*3 int
#define SMEM_TOTAL 210432

// device scratch (no cudaMalloc allowed)
__device__ float              g_sq [B_ * N_];
__device__ unsigned long long g_ext[(size_t)B_ * N_ * 64];  // [row][64] u64: hi(32)|lo(32)

typedef unsigned long long u64;

__device__ __forceinline__ uint32_t smem_u32(const void* p) {
    uint32_t a;
    asm("{ .reg .u64 t; cvta.to.shared.u64 t, %1; cvt.u32.u64 %0, t; }"
        : "=r"(a) : "l"(p));
    return a;
}
__device__ __forceinline__ void cpasync16(uint32_t dst, const void* src) {
    asm volatile("cp.async.cg.shared.global [%0], [%1], 16;" :: "r"(dst), "l"(src));
}
#define CP_COMMIT() asm volatile("cp.async.commit_group;" ::: "memory")
#define CP_WAIT0()  asm volatile("cp.async.wait_group 0;" ::: "memory")

__device__ __forceinline__ void ldsm4(uint32_t& r0, uint32_t& r1,
                                      uint32_t& r2, uint32_t& r3, uint32_t addr) {
    asm volatile("ldmatrix.sync.aligned.m8n8.x4.shared.b16 {%0,%1,%2,%3}, [%4];"
                 : "=r"(r0), "=r"(r1), "=r"(r2), "=r"(r3) : "r"(addr));
}
__device__ __forceinline__ void mma16816(float& d0, float& d1, float& d2, float& d3,
                                         uint32_t a0, uint32_t a1, uint32_t a2, uint32_t a3,
                                         uint32_t b0, uint32_t b1) {
    asm volatile("mma.sync.aligned.m16n8k16.row.col.f32.f16.f16.f32 "
                 "{%0,%1,%2,%3}, {%4,%5,%6,%7}, {%8,%9}, {%0,%1,%2,%3};"
                 : "+f"(d0), "+f"(d1), "+f"(d2), "+f"(d3)
                 : "r"(a0), "r"(a1), "r"(a2), "r"(a3), "r"(b0), "r"(b1));
}

__device__ __forceinline__ void ins3(float s, int m, float* t, int* ix) {
    if (s < t[2]) {
        if (s < t[1]) {
            t[2] = t[1]; ix[2] = ix[1];
            if (s < t[0]) { t[1] = t[0]; ix[1] = ix[0]; t[0] = s; ix[0] = m; }
            else          { t[1] = s; ix[1] = m; }
        } else { t[2] = s; ix[2] = m; }
    }
}

// ---------------------------------------------------------------------------
// prep: squared norms (fp32) + fp16 hi/lo split -> g_ext. one warp per point.
// ---------------------------------------------------------------------------
__global__ void prep_kernel(const float* __restrict__ X) {
    int row  = (blockIdx.x * blockDim.x + threadIdx.x) >> 5;
    int lane = threadIdx.x & 31;
    if (row >= B_ * N_) return;
    float4 v = reinterpret_cast<const float4*>(X)[(size_t)row * 32 + lane];
    float s = v.x * v.x + v.y * v.y + v.z * v.z + v.w * v.w;
    #pragma unroll
    for (int off = 16; off; off >>= 1) s += __shfl_xor_sync(0xffffffffu, s, off);
    if (lane == 0) g_sq[row] = s;

    __half h0 = __float2half_rn(v.x), h1 = __float2half_rn(v.y);
    __half h2 = __float2half_rn(v.z), h3 = __float2half_rn(v.w);
    __half l0 = __float2half_rn(v.x - __half2float(h0));
    __half l1 = __float2half_rn(v.y - __half2float(h1));
    __half l2 = __float2half_rn(v.z - __half2float(h2));
    __half l3 = __float2half_rn(v.w - __half2float(h3));
    u64 hp = (u64)__half_as_ushort(h0)        | ((u64)__half_as_ushort(h1) << 16)
           | ((u64)__half_as_ushort(h2) << 32) | ((u64)__half_as_ushort(h3) << 48);
    u64 lp = (u64)__half_as_ushort(l0)        | ((u64)__half_as_ushort(l1) << 16)
           | ((u64)__half_as_ushort(l2) << 32) | ((u64)__half_as_ushort(l3) << 48);
    g_ext[(size_t)row * 64 + lane]      = hp;   // k 0..127  (hi)
    g_ext[(size_t)row * 64 + 32 + lane] = lp;   // k 128..255 (lo)
}

// ---------------------------------------------------------------------------
// main: mma.sync fp16 3-pass GEMM (R5-identical accumulation order)
//       + in-register top-3 (snapshot merge) + cp.async double buffering.
// grid (16, 32), 512 threads, warp grid 4(m) x 4(n), warp tile 32x32.
// ---------------------------------------------------------------------------
__global__ __launch_bounds__(NT, 1)
void knn_mma_kernel(const float* __restrict__ X,
                    const float* __restrict__ strength,
                    float* __restrict__ Y) {
    extern __shared__ char smem[];
    const uint32_t sb = smem_u32(smem);
    const int tid  = threadIdx.x;
    const int wid  = tid >> 5;
    const int lane = tid & 31;
    const int b     = blockIdx.y;
    const int qbase = blockIdx.x * QT;
    const int xbase = b * N_;

    const uint4* E4 = reinterpret_cast<const uint4*>(g_ext);  // [row][32] 16B chunks
    float* mrgV = (float*)(smem + OFF_MRGV);
    int*   mrgI = (int*)(smem + OFF_MRGI);
    int*   sIdx = (int*)(smem + OFF_SIDX);

    // ---- async load A (query tile) ----
    #pragma unroll
    for (int i = 0; i < 8; i++) {
        int li  = tid + i * NT;
        int row = li >> 5, cc = li & 31;
        cpasync16(sb + OFF_A + row * 512 + ((cc ^ (row & 7)) << 4),
                  &E4[(size_t)(xbase + qbase + row) * 32 + cc]);
    }
    CP_COMMIT();
    // ---- async load B tile 0 ----
    #pragma unroll
    for (int i = 0; i < 8; i++) {
        int li  = tid + i * NT;
        int row = li >> 5, cc = li & 31;
        cpasync16(sb + OFF_B + row * 512 + ((cc ^ (row & 7)) << 4),
                  &E4[(size_t)(xbase + row) * 32 + cc]);
    }
    CP_COMMIT();

    // warp tile position and ldmatrix bases (identical to R5)
    const int m0 = (wid & 3) * 32;
    const int n0 = (wid >> 2) * 32;
    const int rowA = lane & 15;
    const int lcA  = lane >> 4;
    const int rowB = ((lane & 16) >> 1) + (lane & 7);
    const int lcB  = (lane >> 3) & 1;
    const uint32_t rc = (uint32_t)(lane & 7);

    uint32_t aBase[2];
    #pragma unroll
    for (int mi = 0; mi < 2; mi++)
        aBase[mi] = sb + OFF_A + (m0 + mi * 16 + rowA) * 512;

    // per-thread rows (4) and their top-3 lists
    const int rr   = lane >> 2;
    const int colb = (lane & 3) * 2;
    int Rl[4] = {m0 + rr, m0 + rr + 8, m0 + 16 + rr, m0 + 24 + rr};
    float tv[4][3];
    int   ti[4][3];
    #pragma unroll
    for (int r = 0; r < 4; r++) {
        tv[r][0] = tv[r][1] = tv[r][2] = 3.0e38f;
        ti[r][0] = ti[r][1] = ti[r][2] = 0;
    }

    for (int ct = 0; ct < NTILE; ct++) {
        const int cb = ct & 1, nb = (ct + 1) & 1;
        CP_WAIT0();
        __syncthreads();   // tile ct resident; all warps done with buffer nb

        // issue next B tile (overlaps with this tile's MMAs)
        if (ct < NTILE - 1) {
            const int nmb = (ct + 1) * CT;
            #pragma unroll
            for (int i = 0; i < 8; i++) {
                int li  = tid + i * NT;
                int row = li >> 5, cc = li & 31;
                cpasync16(sb + OFF_B + nb * 65536 + row * 512
                          + ((cc ^ (row & 7)) << 4),
                          &E4[(size_t)(xbase + nmb + row) * 32 + cc]);
            }
            CP_COMMIT();
        }

        // candidate sq for my 8 cols
        float2 q[4];
        #pragma unroll
        for (int ni = 0; ni < 4; ni++)
            q[ni] = __ldg(reinterpret_cast<const float2*>(
                        g_sq + xbase + ct * CT + n0 + ni * 8 + colb));

        uint32_t bBase[2];
        #pragma unroll
        for (int ni2 = 0; ni2 < 2; ni2++)
            bBase[ni2] = sb + OFF_B + cb * 65536
                       + (n0 + ni2 * 16 + rowB) * 512;

        // ---- 3-pass MMA, R5-identical ordering: pass-major, k ascending ----
        float d[2][4][4];
        #pragma unroll
        for (int mi = 0; mi < 2; mi++)
            #pragma unroll
            for (int ni = 0; ni < 4; ni++)
                #pragma unroll
                for (int e = 0; e < 4; e++) d[mi][ni][e] = 0.f;

        #pragma unroll
        for (int pss = 0; pss < 3; pss++) {
            const int ab  = (pss == 2) ? 16 : 0;   // A: lo on pass 2
            const int bbc = (pss == 1) ? 16 : 0;   // B: lo on pass 1
            #pragma unroll
            for (int k = 0; k < 8; k++) {
                uint32_t a[2][4], qf[2][4];
                #pragma unroll
                for (int mi = 0; mi < 2; mi++) {
                    uint32_t ch = (uint32_t)(ab + 2 * k + lcA);
                    ldsm4(a[mi][0], a[mi][1], a[mi][2], a[mi][3],
                          aBase[mi] + ((ch ^ rc) << 4));
                }
                #pragma unroll
                for (int ni2 = 0; ni2 < 2; ni2++) {
                    uint32_t ch = (uint32_t)(bbc + 2 * k + lcB);
                    ldsm4(qf[ni2][0], qf[ni2][1], qf[ni2][2], qf[ni2][3],
                          bBase[ni2] + ((ch ^ rc) << 4));
                }
                #pragma unroll
                for (int mi = 0; mi < 2; mi++)
                    #pragma unroll
                    for (int ni = 0; ni < 4; ni++)
                        mma16816(d[mi][ni][0], d[mi][ni][1], d[mi][ni][2], d[mi][ni][3],
                                 a[mi][0], a[mi][1], a[mi][2], a[mi][3],
                                 qf[ni >> 1][(ni & 1) * 2], qf[ni >> 1][(ni & 1) * 2 + 1]);
            }
        }

        // ---- in-register top-3 inserts (32 scores per thread) ----
        #pragma unroll
        for (int mi = 0; mi < 2; mi++)
            #pragma unroll
            for (int eh = 0; eh < 2; eh++) {
                const int ri  = mi * 2 + eh;
                const int ngl = qbase + Rl[ri];
                #pragma unroll
                for (int ni = 0; ni < 4; ni++) {
                    int   m  = ct * CT + n0 + ni * 8 + colb;
                    float s0 = fmaf(-2.f, d[mi][ni][eh * 2],     q[ni].x);
                    float s1 = fmaf(-2.f, d[mi][ni][eh * 2 + 1], q[ni].y);
                    if (m != ngl)     ins3(s0, m,     tv[ri], ti[ri]);
                    if (m + 1 != ngl) ins3(s1, m + 1, tv[ri], ti[ri]);
                }
            }
    }

    // ---- merge across the 4 lanes sharing each row (offsets 1, 2) ----
    // SNAPSHOT all three partner pairs BEFORE inserting: inserting while
    // shuffling reads the partner's already-mutated list (R6/R8 bug: a true
    // neighbor gets dropped; one flipped index = 1.3e-3 rel_err).
    #pragma unroll
    for (int off = 1; off <= 2; off <<= 1) {
        #pragma unroll
        for (int r = 0; r < 4; r++) {
            float sv[3]; int si[3];
            #pragma unroll
            for (int e = 0; e < 3; e++) {
                sv[e] = __shfl_xor_sync(0xffffffffu, tv[r][e], off);
                si[e] = __shfl_xor_sync(0xffffffffu, ti[r][e], off);
            }
            #pragma unroll
            for (int e = 0; e < 3; e++)
                ins3(sv[e], si[e], tv[r], ti[r]);
        }
    }
    // publish per-warp top-3 (4 n-warps per row)
    if ((lane & 3) == 0) {
        const int nw = wid >> 2;
        #pragma unroll
        for (int r = 0; r < 4; r++) {
            int base = (Rl[r] * 4 + nw) * 3;
            #pragma unroll
            for (int e = 0; e < 3; e++) {
                mrgV[base + e] = tv[r][e];
                mrgI[base + e] = ti[r][e];
            }
        }
    }
    __syncthreads();

    // final merge: one thread per row (sequential smem reads — no race)
    if (tid < QT) {
        float ft[3] = {3.0e38f, 3.0e38f, 3.0e38f};
        int   fi[3] = {0, 0, 0};
        #pragma unroll
        for (int nw = 0; nw < 4; nw++) {
            int base = (tid * 4 + nw) * 3;
            #pragma unroll
            for (int e = 0; e < 3; e++)
                ins3(mrgV[base + e], mrgI[base + e], ft, fi);
        }
        sIdx[tid * 3 + 0] = fi[0];
        sIdx[tid * 3 + 1] = fi[1];
        sIdx[tid * 3 + 2] = fi[2];
    }
    __syncthreads();

    // ---- gather + blend: (1-s)*x + (s/3)*(xa+xb+xc), original fp32 data ----
    float s  = fminf(fmaxf(strength[0], 0.f), 1.f);
    float w1 = 1.f - s;
    float w2 = s * (1.f / 3.f);
    const float4* X4 = reinterpret_cast<const float4*>(X + (size_t)b * N_ * D_);
    float* Yb = Y + (size_t)b * N_ * D_;
    for (int r = wid; r < QT; r += NT / 32) {
        int n  = qbase + r;
        int ia = sIdx[r * 3 + 0];
        int ib = sIdx[r * 3 + 1];
        int ic = sIdx[r * 3 + 2];
        float4 vn = X4[(size_t)n  * 32 + lane];
        float4 va = X4[(size_t)ia * 32 + lane];
        float4 vb = X4[(size_t)ib * 32 + lane];
        float4 vc = X4[(size_t)ic * 32 + lane];
        float4 o;
        o.x = w1 * vn.x + w2 * (va.x + vb.x + vc.x);
        o.y = w1 * vn.y + w2 * (va.y + vb.y + vc.y);
        o.z = w1 * vn.z + w2 * (va.z + vb.z + vc.z);
        o.w = w1 * vn.w + w2 * (va.w + vb.w + vc.w);
        reinterpret_cast<float4*>(Yb + (size_t)n * D_)[lane] = o;
    }
}

// ---------------------------------------------------------------------------
extern "C" void kernel_launch(void* const* d_in, const int* in_sizes, int n_in,
                              void* d_out, int out_size) {
    const float* X;
    const float* st;
    if (n_in >= 2 && in_sizes[0] == 1) { st = (const float*)d_in[0]; X = (const float*)d_in[1]; }
    else                               { X = (const float*)d_in[0]; st = (const float*)d_in[1]; }
    float* Y = (float*)d_out;

    int rows = B_ * N_;
    prep_kernel<<<(rows * 32 + 255) / 256, 256>>>(X);

    cudaFuncSetAttribute(knn_mma_kernel,
                         cudaFuncAttributeMaxDynamicSharedMemorySize, SMEM_TOTAL);
    dim3 grid(N_ / QT, B_);
    knn_mma_kernel<<<grid, NT, SMEM_TOTAL>>>(X, st, Y);
}

// round 10
// speedup vs baseline: 3.3160x; 1.1712x over previous
#include <cuda_runtime.h>
#include <cuda_fp16.h>
#include <cstdint>

// Problem constants (ParacrineCascade: B=32, N=2048, D=128, K=3)
#define B_     32
#define N_     2048
#define D_     128
#define QT     128                // queries per CTA
#define CT     128                // candidates per tile
#define NTILE  (N_ / CT)          // 16
#define NT     512                // threads

// smem byte offsets
#define OFF_A    0                // 64KB  query tile (K=256 fp16, swizzled)
#define OFF_B    65536            // 2 x 64KB candidate tiles
#define OFF_MRGV 196608           // 128*4*3 f32 = 6KB
#define OFF_MRGI 202752           // 128*4*3 int = 6KB
#define OFF_SIDX 208896           // 128*3 int
#define SMEM_TOTAL 210432

// device scratch (no cudaMalloc allowed)
__device__ float              g_sq [B_ * N_];
__device__ unsigned long long g_ext[(size_t)B_ * N_ * 64];  // [row][64] u64: hi(32)|lo(32)

typedef unsigned long long u64;

__device__ __forceinline__ uint32_t smem_u32(const void* p) {
    uint32_t a;
    asm("{ .reg .u64 t; cvta.to.shared.u64 t, %1; cvt.u32.u64 %0, t; }"
        : "=r"(a) : "l"(p));
    return a;
}
__device__ __forceinline__ void cpasync16(uint32_t dst, const void* src) {
    asm volatile("cp.async.cg.shared.global [%0], [%1], 16;" :: "r"(dst), "l"(src));
}
#define CP_COMMIT() asm volatile("cp.async.commit_group;" ::: "memory")
#define CP_WAIT0()  asm volatile("cp.async.wait_group 0;" ::: "memory")

__device__ __forceinline__ void ldsm4(uint32_t& r0, uint32_t& r1,
                                      uint32_t& r2, uint32_t& r3, uint32_t addr) {
    asm volatile("ldmatrix.sync.aligned.m8n8.x4.shared.b16 {%0,%1,%2,%3}, [%4];"
                 : "=r"(r0), "=r"(r1), "=r"(r2), "=r"(r3) : "r"(addr));
}
__device__ __forceinline__ void mma16816(float& d0, float& d1, float& d2, float& d3,
                                         uint32_t a0, uint32_t a1, uint32_t a2, uint32_t a3,
                                         uint32_t b0, uint32_t b1) {
    asm volatile("mma.sync.aligned.m16n8k16.row.col.f32.f16.f16.f32 "
                 "{%0,%1,%2,%3}, {%4,%5,%6,%7}, {%8,%9}, {%0,%1,%2,%3};"
                 : "+f"(d0), "+f"(d1), "+f"(d2), "+f"(d3)
                 : "r"(a0), "r"(a1), "r"(a2), "r"(a3), "r"(b0), "r"(b1));
}

__device__ __forceinline__ void ins3(float s, int m, float* t, int* ix) {
    if (s < t[2]) {
        if (s < t[1]) {
            t[2] = t[1]; ix[2] = ix[1];
            if (s < t[0]) { t[1] = t[0]; ix[1] = ix[0]; t[0] = s; ix[0] = m; }
            else          { t[1] = s; ix[1] = m; }
        } else { t[2] = s; ix[2] = m; }
    }
}

// ---------------------------------------------------------------------------
// prep: squared norms (fp32) + fp16 hi/lo split -> g_ext. one warp per point.
// ---------------------------------------------------------------------------
__global__ void prep_kernel(const float* __restrict__ X) {
    int row  = (blockIdx.x * blockDim.x + threadIdx.x) >> 5;
    int lane = threadIdx.x & 31;
    if (row >= B_ * N_) return;
    float4 v = reinterpret_cast<const float4*>(X)[(size_t)row * 32 + lane];
    float s = v.x * v.x + v.y * v.y + v.z * v.z + v.w * v.w;
    #pragma unroll
    for (int off = 16; off; off >>= 1) s += __shfl_xor_sync(0xffffffffu, s, off);
    if (lane == 0) g_sq[row] = s;

    __half h0 = __float2half_rn(v.x), h1 = __float2half_rn(v.y);
    __half h2 = __float2half_rn(v.z), h3 = __float2half_rn(v.w);
    __half l0 = __float2half_rn(v.x - __half2float(h0));
    __half l1 = __float2half_rn(v.y - __half2float(h1));
    __half l2 = __float2half_rn(v.z - __half2float(h2));
    __half l3 = __float2half_rn(v.w - __half2float(h3));
    u64 hp = (u64)__half_as_ushort(h0)        | ((u64)__half_as_ushort(h1) << 16)
           | ((u64)__half_as_ushort(h2) << 32) | ((u64)__half_as_ushort(h3) << 48);
    u64 lp = (u64)__half_as_ushort(l0)        | ((u64)__half_as_ushort(l1) << 16)
           | ((u64)__half_as_ushort(l2) << 32) | ((u64)__half_as_ushort(l3) << 48);
    g_ext[(size_t)row * 64 + lane]      = hp;   // k 0..127  (hi)
    g_ext[(size_t)row * 64 + 32 + lane] = lp;   // k 128..255 (lo)
}

// ---------------------------------------------------------------------------
// main: mma.sync fp16 3-term GEMM, interleaved per-k fragment loading
//       (R6-identical accumulation order — proven same top-3 as R5 by the
//       R6/R8 identical-error experiment), in-register top-3 with snapshot
//       merge, cp.async double-buffered B.
// grid (16, 32), 512 threads, warp grid 4(m) x 4(n), warp tile 32x32.
// ---------------------------------------------------------------------------
__global__ __launch_bounds__(NT, 1)
void knn_mma_kernel(const float* __restrict__ X,
                    const float* __restrict__ strength,
                    float* __restrict__ Y) {
    extern __shared__ char smem[];
    const uint32_t sb = smem_u32(smem);
    const int tid  = threadIdx.x;
    const int wid  = tid >> 5;
    const int lane = tid & 31;
    const int b     = blockIdx.y;
    const int qbase = blockIdx.x * QT;
    const int xbase = b * N_;

    const uint4* E4 = reinterpret_cast<const uint4*>(g_ext);  // [row][32] 16B chunks
    float* mrgV = (float*)(smem + OFF_MRGV);
    int*   mrgI = (int*)(smem + OFF_MRGI);
    int*   sIdx = (int*)(smem + OFF_SIDX);

    // ---- async load A (query tile) ----
    #pragma unroll
    for (int i = 0; i < 8; i++) {
        int li  = tid + i * NT;
        int row = li >> 5, cc = li & 31;
        cpasync16(sb + OFF_A + row * 512 + ((cc ^ (row & 7)) << 4),
                  &E4[(size_t)(xbase + qbase + row) * 32 + cc]);
    }
    CP_COMMIT();
    // ---- async load B tile 0 ----
    #pragma unroll
    for (int i = 0; i < 8; i++) {
        int li  = tid + i * NT;
        int row = li >> 5, cc = li & 31;
        cpasync16(sb + OFF_B + row * 512 + ((cc ^ (row & 7)) << 4),
                  &E4[(size_t)(xbase + row) * 32 + cc]);
    }
    CP_COMMIT();

    // warp tile position and ldmatrix bases
    const int m0 = (wid & 3) * 32;
    const int n0 = (wid >> 2) * 32;
    const int rowA = lane & 15;
    const int lcA  = lane >> 4;
    const int rowB = ((lane & 16) >> 1) + (lane & 7);
    const int lcB  = (lane >> 3) & 1;
    const uint32_t rc = (uint32_t)(lane & 7);

    uint32_t aBase[2];
    #pragma unroll
    for (int mi = 0; mi < 2; mi++)
        aBase[mi] = sb + OFF_A + (m0 + mi * 16 + rowA) * 512;

    // per-thread rows (4) and their top-3 lists
    const int rr   = lane >> 2;
    const int colb = (lane & 3) * 2;
    int Rl[4] = {m0 + rr, m0 + rr + 8, m0 + 16 + rr, m0 + 24 + rr};
    float tv[4][3];
    int   ti[4][3];
    #pragma unroll
    for (int r = 0; r < 4; r++) {
        tv[r][0] = tv[r][1] = tv[r][2] = 3.0e38f;
        ti[r][0] = ti[r][1] = ti[r][2] = 0;
    }

    for (int ct = 0; ct < NTILE; ct++) {
        const int cb = ct & 1, nb = (ct + 1) & 1;
        CP_WAIT0();
        __syncthreads();   // tile ct resident; all warps done with buffer nb

        // issue next B tile (overlaps with this tile's MMAs)
        if (ct < NTILE - 1) {
            const int nmb = (ct + 1) * CT;
            #pragma unroll
            for (int i = 0; i < 8; i++) {
                int li  = tid + i * NT;
                int row = li >> 5, cc = li & 31;
                cpasync16(sb + OFF_B + nb * 65536 + row * 512
                          + ((cc ^ (row & 7)) << 4),
                          &E4[(size_t)(xbase + nmb + row) * 32 + cc]);
            }
            CP_COMMIT();
        }

        // candidate sq for my 8 cols
        float2 q[4];
        #pragma unroll
        for (int ni = 0; ni < 4; ni++)
            q[ni] = __ldg(reinterpret_cast<const float2*>(
                        g_sq + xbase + ct * CT + n0 + ni * 8 + colb));

        uint32_t bBase[2];
        #pragma unroll
        for (int ni2 = 0; ni2 < 2; ni2++)
            bBase[ni2] = sb + OFF_B + cb * 65536
                       + (n0 + ni2 * 16 + rowB) * 512;

        // ---- interleaved 3-term MMA: load fragments once per k ----
        float d[2][4][4];
        #pragma unroll
        for (int mi = 0; mi < 2; mi++)
            #pragma unroll
            for (int ni = 0; ni < 4; ni++)
                #pragma unroll
                for (int e = 0; e < 4; e++) d[mi][ni][e] = 0.f;

        #pragma unroll
        for (int k = 0; k < 8; k++) {
            const uint32_t chA = (uint32_t)(2 * k + lcA);
            const uint32_t chB = (uint32_t)(2 * k + lcB);
            uint32_t ah[2][4], al[2][4], bh[2][4], bl[2][4];
            #pragma unroll
            for (int mi = 0; mi < 2; mi++) {
                ldsm4(ah[mi][0], ah[mi][1], ah[mi][2], ah[mi][3],
                      aBase[mi] + ((chA ^ rc) << 4));
                ldsm4(al[mi][0], al[mi][1], al[mi][2], al[mi][3],
                      aBase[mi] + (((chA + 16) ^ rc) << 4));
            }
            #pragma unroll
            for (int ni2 = 0; ni2 < 2; ni2++) {
                ldsm4(bh[ni2][0], bh[ni2][1], bh[ni2][2], bh[ni2][3],
                      bBase[ni2] + ((chB ^ rc) << 4));
                ldsm4(bl[ni2][0], bl[ni2][1], bl[ni2][2], bl[ni2][3],
                      bBase[ni2] + (((chB + 16) ^ rc) << 4));
            }
            #pragma unroll
            for (int mi = 0; mi < 2; mi++)
                #pragma unroll
                for (int ni = 0; ni < 4; ni++) {
                    uint32_t b0h = bh[ni >> 1][(ni & 1) * 2];
                    uint32_t b1h = bh[ni >> 1][(ni & 1) * 2 + 1];
                    uint32_t b0l = bl[ni >> 1][(ni & 1) * 2];
                    uint32_t b1l = bl[ni >> 1][(ni & 1) * 2 + 1];
                    mma16816(d[mi][ni][0], d[mi][ni][1], d[mi][ni][2], d[mi][ni][3],
                             ah[mi][0], ah[mi][1], ah[mi][2], ah[mi][3], b0h, b1h);
                    mma16816(d[mi][ni][0], d[mi][ni][1], d[mi][ni][2], d[mi][ni][3],
                             ah[mi][0], ah[mi][1], ah[mi][2], ah[mi][3], b0l, b1l);
                    mma16816(d[mi][ni][0], d[mi][ni][1], d[mi][ni][2], d[mi][ni][3],
                             al[mi][0], al[mi][1], al[mi][2], al[mi][3], b0h, b1h);
                }
        }

        // ---- in-register top-3 inserts (32 scores per thread) ----
        #pragma unroll
        for (int mi = 0; mi < 2; mi++)
            #pragma unroll
            for (int eh = 0; eh < 2; eh++) {
                const int ri  = mi * 2 + eh;
                const int ngl = qbase + Rl[ri];
                #pragma unroll
                for (int ni = 0; ni < 4; ni++) {
                    int   m  = ct * CT + n0 + ni * 8 + colb;
                    float s0 = fmaf(-2.f, d[mi][ni][eh * 2],     q[ni].x);
                    float s1 = fmaf(-2.f, d[mi][ni][eh * 2 + 1], q[ni].y);
                    if (m != ngl)     ins3(s0, m,     tv[ri], ti[ri]);
                    if (m + 1 != ngl) ins3(s1, m + 1, tv[ri], ti[ri]);
                }
            }
    }

    // ---- merge across the 4 lanes sharing each row: SNAPSHOT then insert ----
    #pragma unroll
    for (int off = 1; off <= 2; off <<= 1) {
        #pragma unroll
        for (int r = 0; r < 4; r++) {
            float sv[3]; int si[3];
            #pragma unroll
            for (int e = 0; e < 3; e++) {
                sv[e] = __shfl_xor_sync(0xffffffffu, tv[r][e], off);
                si[e] = __shfl_xor_sync(0xffffffffu, ti[r][e], off);
            }
            #pragma unroll
            for (int e = 0; e < 3; e++)
                ins3(sv[e], si[e], tv[r], ti[r]);
        }
    }
    // publish per-warp top-3 (4 n-warps per row)
    if ((lane & 3) == 0) {
        const int nw = wid >> 2;
        #pragma unroll
        for (int r = 0; r < 4; r++) {
            int base = (Rl[r] * 4 + nw) * 3;
            #pragma unroll
            for (int e = 0; e < 3; e++) {
                mrgV[base + e] = tv[r][e];
                mrgI[base + e] = ti[r][e];
            }
        }
    }
    __syncthreads();

    // final merge: one thread per row (sequential smem reads — no race)
    if (tid < QT) {
        float ft[3] = {3.0e38f, 3.0e38f, 3.0e38f};
        int   fi[3] = {0, 0, 0};
        #pragma unroll
        for (int nw = 0; nw < 4; nw++) {
            int base = (tid * 4 + nw) * 3;
            #pragma unroll
            for (int e = 0; e < 3; e++)
                ins3(mrgV[base + e], mrgI[base + e], ft, fi);
        }
        sIdx[tid * 3 + 0] = fi[0];
        sIdx[tid * 3 + 1] = fi[1];
        sIdx[tid * 3 + 2] = fi[2];
    }
    __syncthreads();

    // ---- gather + blend: (1-s)*x + (s/3)*(xa+xb+xc), original fp32 data ----
    float s  = fminf(fmaxf(strength[0], 0.f), 1.f);
    float w1 = 1.f - s;
    float w2 = s * (1.f / 3.f);
    const float4* X4 = reinterpret_cast<const float4*>(X + (size_t)b * N_ * D_);
    float* Yb = Y + (size_t)b * N_ * D_;
    for (int r = wid; r < QT; r += NT / 32) {
        int n  = qbase + r;
        int ia = sIdx[r * 3 + 0];
        int ib = sIdx[r * 3 + 1];
        int ic = sIdx[r * 3 + 2];
        float4 vn = X4[(size_t)n  * 32 + lane];
        float4 va = X4[(size_t)ia * 32 + lane];
        float4 vb = X4[(size_t)ib * 32 + lane];
        float4 vc = X4[(size_t)ic * 32 + lane];
        float4 o;
        o.x = w1 * vn.x + w2 * (va.x + vb.x + vc.x);
        o.y = w1 * vn.y + w2 * (va.y + vb.y + vc.y);
        o.z = w1 * vn.z + w2 * (va.z + vb.z + vc.z);
        o.w = w1 * vn.w + w2 * (va.w + vb.w + vc.w);
        reinterpret_cast<float4*>(Yb + (size_t)n * D_)[lane] = o;
    }
}

// ---------------------------------------------------------------------------
extern "C" void kernel_launch(void* const* d_in, const int* in_sizes, int n_in,
                              void* d_out, int out_size) {
    const float* X;
    const float* st;
    if (n_in >= 2 && in_sizes[0] == 1) { st = (const float*)d_in[0]; X = (const float*)d_in[1]; }
    else                               { X = (const float*)d_in[0]; st = (const float*)d_in[1]; }
    float* Y = (float*)d_out;

    int rows = B_ * N_;
    prep_kernel<<<(rows * 32 + 255) / 256, 256>>>(X);

    cudaFuncSetAttribute(knn_mma_kernel,
                         cudaFuncAttributeMaxDynamicSharedMemorySize, SMEM_TOTAL);
    dim3 grid(N_ / QT, B_);
    knn_mma_kernel<<<grid, NT, SMEM_TOTAL>>>(X, st, Y);
}

// round 11
// speedup vs baseline: 6.2126x; 1.8735x over previous
#include <cuda_runtime.h>
#include <cuda_fp16.h>
#include <cstdint>

// Problem constants (ParacrineCascade: B=32, N=2048, D=128, K=3)
#define B_     32
#define N_     2048
#define D_     128
#define QT     64                 // queries per CTA  (2 CTAs/SM)
#define CT     128                // candidates per tile
#define NTILE  (N_ / CT)          // 16
#define NT     256                // threads (8 warps: 2m x 4n, warp tile 32x32)

// smem byte offsets
#define OFF_A    0                // 32KB  query tile (64 rows x 512B)
#define OFF_B    32768            // 64KB  candidate tile (single buffer)
#define OFF_MRGV 98304            // 64*4*3 f32 = 3072
#define OFF_MRGI 101376           // 64*4*3 int = 3072
#define OFF_SIDX 104448           // 64*3 int = 768
#define SMEM_TOTAL 105472         // ~103KB -> 2 CTAs/SM

// device scratch (no cudaMalloc allowed)
__device__ float              g_sq [B_ * N_];
__device__ unsigned long long g_ext[(size_t)B_ * N_ * 64];  // [row][64] u64: hi(32)|lo(32)

typedef unsigned long long u64;

__device__ __forceinline__ uint32_t smem_u32(const void* p) {
    uint32_t a;
    asm("{ .reg .u64 t; cvta.to.shared.u64 t, %1; cvt.u32.u64 %0, t; }"
        : "=r"(a) : "l"(p));
    return a;
}
__device__ __forceinline__ void cpasync16(uint32_t dst, const void* src) {
    asm volatile("cp.async.cg.shared.global [%0], [%1], 16;" :: "r"(dst), "l"(src));
}
#define CP_COMMIT() asm volatile("cp.async.commit_group;" ::: "memory")
#define CP_WAIT0()  asm volatile("cp.async.wait_group 0;" ::: "memory")

__device__ __forceinline__ void ldsm4(uint32_t& r0, uint32_t& r1,
                                      uint32_t& r2, uint32_t& r3, uint32_t addr) {
    asm volatile("ldmatrix.sync.aligned.m8n8.x4.shared.b16 {%0,%1,%2,%3}, [%4];"
                 : "=r"(r0), "=r"(r1), "=r"(r2), "=r"(r3) : "r"(addr));
}
__device__ __forceinline__ void mma16816(float& d0, float& d1, float& d2, float& d3,
                                         uint32_t a0, uint32_t a1, uint32_t a2, uint32_t a3,
                                         uint32_t b0, uint32_t b1) {
    asm volatile("mma.sync.aligned.m16n8k16.row.col.f32.f16.f16.f32 "
                 "{%0,%1,%2,%3}, {%4,%5,%6,%7}, {%8,%9}, {%0,%1,%2,%3};"
                 : "+f"(d0), "+f"(d1), "+f"(d2), "+f"(d3)
                 : "r"(a0), "r"(a1), "r"(a2), "r"(a3), "r"(b0), "r"(b1));
}

__device__ __forceinline__ void ins3(float s, int m, float* t, int* ix) {
    if (s < t[2]) {
        if (s < t[1]) {
            t[2] = t[1]; ix[2] = ix[1];
            if (s < t[0]) { t[1] = t[0]; ix[1] = ix[0]; t[0] = s; ix[0] = m; }
            else          { t[1] = s; ix[1] = m; }
        } else { t[2] = s; ix[2] = m; }
    }
}

// ---------------------------------------------------------------------------
// prep: squared norms (fp32) + fp16 hi/lo split -> g_ext. one warp per point.
// ---------------------------------------------------------------------------
__global__ void prep_kernel(const float* __restrict__ X) {
    int row  = (blockIdx.x * blockDim.x + threadIdx.x) >> 5;
    int lane = threadIdx.x & 31;
    if (row >= B_ * N_) return;
    float4 v = reinterpret_cast<const float4*>(X)[(size_t)row * 32 + lane];
    float s = v.x * v.x + v.y * v.y + v.z * v.z + v.w * v.w;
    #pragma unroll
    for (int off = 16; off; off >>= 1) s += __shfl_xor_sync(0xffffffffu, s, off);
    if (lane == 0) g_sq[row] = s;

    __half h0 = __float2half_rn(v.x), h1 = __float2half_rn(v.y);
    __half h2 = __float2half_rn(v.z), h3 = __float2half_rn(v.w);
    __half l0 = __float2half_rn(v.x - __half2float(h0));
    __half l1 = __float2half_rn(v.y - __half2float(h1));
    __half l2 = __float2half_rn(v.z - __half2float(h2));
    __half l3 = __float2half_rn(v.w - __half2float(h3));
    u64 hp = (u64)__half_as_ushort(h0)        | ((u64)__half_as_ushort(h1) << 16)
           | ((u64)__half_as_ushort(h2) << 32) | ((u64)__half_as_ushort(h3) << 48);
    u64 lp = (u64)__half_as_ushort(l0)        | ((u64)__half_as_ushort(l1) << 16)
           | ((u64)__half_as_ushort(l2) << 32) | ((u64)__half_as_ushort(l3) << 48);
    g_ext[(size_t)row * 64 + lane]      = hp;   // k 0..127  (hi)
    g_ext[(size_t)row * 64 + 32 + lane] = lp;   // k 128..255 (lo)
}

// ---------------------------------------------------------------------------
// main: mma.sync fp16 3-term GEMM (R10-identical per-dot arithmetic + order),
//       in-register top-3 with snapshot merge, single-buffer B + cp.async
//       overlapped with epilogue, 2 CTAs/SM.
// grid (32, 32), 256 threads, warp grid 2(m) x 4(n), warp tile 32x32.
// ---------------------------------------------------------------------------
__global__ __launch_bounds__(NT, 2)
void knn_mma_kernel(const float* __restrict__ X,
                    const float* __restrict__ strength,
                    float* __restrict__ Y) {
    extern __shared__ char smem[];
    const uint32_t sb = smem_u32(smem);
    const int tid  = threadIdx.x;
    const int wid  = tid >> 5;
    const int lane = tid & 31;
    const int b     = blockIdx.y;
    const int qbase = blockIdx.x * QT;
    const int xbase = b * N_;

    const uint4* E4 = reinterpret_cast<const uint4*>(g_ext);  // [row][32] 16B chunks
    float* mrgV = (float*)(smem + OFF_MRGV);
    int*   mrgI = (int*)(smem + OFF_MRGI);
    int*   sIdx = (int*)(smem + OFF_SIDX);

    // ---- async load A (query tile: 64 rows x 32 chunks) ----
    #pragma unroll
    for (int i = 0; i < 8; i++) {
        int li  = tid + i * NT;
        int row = li >> 5, cc = li & 31;
        cpasync16(sb + OFF_A + row * 512 + ((cc ^ (row & 7)) << 4),
                  &E4[(size_t)(xbase + qbase + row) * 32 + cc]);
    }
    // ---- async load B tile 0 (128 rows x 32 chunks) ----
    #pragma unroll
    for (int i = 0; i < 16; i++) {
        int li  = tid + i * NT;
        int row = li >> 5, cc = li & 31;
        cpasync16(sb + OFF_B + row * 512 + ((cc ^ (row & 7)) << 4),
                  &E4[(size_t)(xbase + row) * 32 + cc]);
    }
    CP_COMMIT();

    // warp tile position and ldmatrix bases
    const int m0 = (wid & 1) * 32;          // 2 m-warps
    const int n0 = (wid >> 1) * 32;         // 4 n-warps
    const int rowA = lane & 15;
    const int lcA  = lane >> 4;
    const int rowB = ((lane & 16) >> 1) + (lane & 7);
    const int lcB  = (lane >> 3) & 1;
    const uint32_t rc = (uint32_t)(lane & 7);

    uint32_t aBase[2];
    #pragma unroll
    for (int mi = 0; mi < 2; mi++)
        aBase[mi] = sb + OFF_A + (m0 + mi * 16 + rowA) * 512;
    uint32_t bBase[2];
    #pragma unroll
    for (int ni2 = 0; ni2 < 2; ni2++)
        bBase[ni2] = sb + OFF_B + (n0 + ni2 * 16 + rowB) * 512;

    // per-thread rows (4) and their top-3 lists
    const int rr   = lane >> 2;
    const int colb = (lane & 3) * 2;
    int Rl[4] = {m0 + rr, m0 + rr + 8, m0 + 16 + rr, m0 + 24 + rr};
    float tv[4][3];
    int   ti[4][3];
    #pragma unroll
    for (int r = 0; r < 4; r++) {
        tv[r][0] = tv[r][1] = tv[r][2] = 3.0e38f;
        ti[r][0] = ti[r][1] = ti[r][2] = 0;
    }

    CP_WAIT0();
    __syncthreads();   // A + B0 resident

    for (int ct = 0; ct < NTILE; ct++) {
        // candidate sq for my 8 cols (issued early; latency hidden by MMAs)
        float2 q[4];
        #pragma unroll
        for (int ni = 0; ni < 4; ni++)
            q[ni] = __ldg(reinterpret_cast<const float2*>(
                        g_sq + xbase + ct * CT + n0 + ni * 8 + colb));

        // ---- interleaved 3-term MMA: load fragments once per k ----
        float d[2][4][4];
        #pragma unroll
        for (int mi = 0; mi < 2; mi++)
            #pragma unroll
            for (int ni = 0; ni < 4; ni++)
                #pragma unroll
                for (int e = 0; e < 4; e++) d[mi][ni][e] = 0.f;

        #pragma unroll
        for (int k = 0; k < 8; k++) {
            const uint32_t chA = (uint32_t)(2 * k + lcA);
            const uint32_t chB = (uint32_t)(2 * k + lcB);
            uint32_t ah[2][4], al[2][4], bh[2][4], bl[2][4];
            #pragma unroll
            for (int mi = 0; mi < 2; mi++) {
                ldsm4(ah[mi][0], ah[mi][1], ah[mi][2], ah[mi][3],
                      aBase[mi] + ((chA ^ rc) << 4));
                ldsm4(al[mi][0], al[mi][1], al[mi][2], al[mi][3],
                      aBase[mi] + (((chA + 16) ^ rc) << 4));
            }
            #pragma unroll
            for (int ni2 = 0; ni2 < 2; ni2++) {
                ldsm4(bh[ni2][0], bh[ni2][1], bh[ni2][2], bh[ni2][3],
                      bBase[ni2] + ((chB ^ rc) << 4));
                ldsm4(bl[ni2][0], bl[ni2][1], bl[ni2][2], bl[ni2][3],
                      bBase[ni2] + (((chB + 16) ^ rc) << 4));
            }
            #pragma unroll
            for (int mi = 0; mi < 2; mi++)
                #pragma unroll
                for (int ni = 0; ni < 4; ni++) {
                    uint32_t b0h = bh[ni >> 1][(ni & 1) * 2];
                    uint32_t b1h = bh[ni >> 1][(ni & 1) * 2 + 1];
                    uint32_t b0l = bl[ni >> 1][(ni & 1) * 2];
                    uint32_t b1l = bl[ni >> 1][(ni & 1) * 2 + 1];
                    mma16816(d[mi][ni][0], d[mi][ni][1], d[mi][ni][2], d[mi][ni][3],
                             ah[mi][0], ah[mi][1], ah[mi][2], ah[mi][3], b0h, b1h);
                    mma16816(d[mi][ni][0], d[mi][ni][1], d[mi][ni][2], d[mi][ni][3],
                             ah[mi][0], ah[mi][1], ah[mi][2], ah[mi][3], b0l, b1l);
                    mma16816(d[mi][ni][0], d[mi][ni][1], d[mi][ni][2], d[mi][ni][3],
                             al[mi][0], al[mi][1], al[mi][2], al[mi][3], b0h, b1h);
                }
        }

        __syncthreads();   // all warps done reading B[ct] from smem

        // issue next B tile into the (now free) single buffer;
        // overlaps with the epilogue below
        if (ct < NTILE - 1) {
            const int nmb = (ct + 1) * CT;
            #pragma unroll
            for (int i = 0; i < 16; i++) {
                int li  = tid + i * NT;
                int row = li >> 5, cc = li & 31;
                cpasync16(sb + OFF_B + row * 512 + ((cc ^ (row & 7)) << 4),
                          &E4[(size_t)(xbase + nmb + row) * 32 + cc]);
            }
            CP_COMMIT();
        }

        // ---- in-register top-3 inserts (32 scores per thread) ----
        #pragma unroll
        for (int mi = 0; mi < 2; mi++)
            #pragma unroll
            for (int eh = 0; eh < 2; eh++) {
                const int ri  = mi * 2 + eh;
                const int ngl = qbase + Rl[ri];
                #pragma unroll
                for (int ni = 0; ni < 4; ni++) {
                    int   m  = ct * CT + n0 + ni * 8 + colb;
                    float s0 = fmaf(-2.f, d[mi][ni][eh * 2],     q[ni].x);
                    float s1 = fmaf(-2.f, d[mi][ni][eh * 2 + 1], q[ni].y);
                    if (m != ngl)     ins3(s0, m,     tv[ri], ti[ri]);
                    if (m + 1 != ngl) ins3(s1, m + 1, tv[ri], ti[ri]);
                }
            }

        CP_WAIT0();
        __syncthreads();   // B[ct+1] resident for everyone
    }

    // ---- merge across the 4 lanes sharing each row: SNAPSHOT then insert ----
    #pragma unroll
    for (int off = 1; off <= 2; off <<= 1) {
        #pragma unroll
        for (int r = 0; r < 4; r++) {
            float sv[3]; int si[3];
            #pragma unroll
            for (int e = 0; e < 3; e++) {
                sv[e] = __shfl_xor_sync(0xffffffffu, tv[r][e], off);
                si[e] = __shfl_xor_sync(0xffffffffu, ti[r][e], off);
            }
            #pragma unroll
            for (int e = 0; e < 3; e++)
                ins3(sv[e], si[e], tv[r], ti[r]);
        }
    }
    // publish per-warp top-3 (4 n-warps per row)
    if ((lane & 3) == 0) {
        const int nw = wid >> 1;
        #pragma unroll
        for (int r = 0; r < 4; r++) {
            int base = (Rl[r] * 4 + nw) * 3;
            #pragma unroll
            for (int e = 0; e < 3; e++) {
                mrgV[base + e] = tv[r][e];
                mrgI[base + e] = ti[r][e];
            }
        }
    }
    __syncthreads();

    // final merge: one thread per row (sequential smem reads — no race)
    if (tid < QT) {
        float ft[3] = {3.0e38f, 3.0e38f, 3.0e38f};
        int   fi[3] = {0, 0, 0};
        #pragma unroll
        for (int nw = 0; nw < 4; nw++) {
            int base = (tid * 4 + nw) * 3;
            #pragma unroll
            for (int e = 0; e < 3; e++)
                ins3(mrgV[base + e], mrgI[base + e], ft, fi);
        }
        sIdx[tid * 3 + 0] = fi[0];
        sIdx[tid * 3 + 1] = fi[1];
        sIdx[tid * 3 + 2] = fi[2];
    }
    __syncthreads();

    // ---- gather + blend: (1-s)*x + (s/3)*(xa+xb+xc), original fp32 data ----
    float s  = fminf(fmaxf(strength[0], 0.f), 1.f);
    float w1 = 1.f - s;
    float w2 = s * (1.f / 3.f);
    const float4* X4 = reinterpret_cast<const float4*>(X + (size_t)b * N_ * D_);
    float* Yb = Y + (size_t)b * N_ * D_;
    for (int r = wid; r < QT; r += NT / 32) {
        int n  = qbase + r;
        int ia = sIdx[r * 3 + 0];
        int ib = sIdx[r * 3 + 1];
        int ic = sIdx[r * 3 + 2];
        float4 vn = X4[(size_t)n  * 32 + lane];
        float4 va = X4[(size_t)ia * 32 + lane];
        float4 vb = X4[(size_t)ib * 32 + lane];
        float4 vc = X4[(size_t)ic * 32 + lane];
        float4 o;
        o.x = w1 * vn.x + w2 * (va.x + vb.x + vc.x);
        o.y = w1 * vn.y + w2 * (va.y + vb.y + vc.y);
        o.z = w1 * vn.z + w2 * (va.z + vb.z + vc.z);
        o.w = w1 * vn.w + w2 * (va.w + vb.w + vc.w);
        reinterpret_cast<float4*>(Yb + (size_t)n * D_)[lane] = o;
    }
}

// ---------------------------------------------------------------------------
extern "C" void kernel_launch(void* const* d_in, const int* in_sizes, int n_in,
                              void* d_out, int out_size) {
    const float* X;
    const float* st;
    if (n_in >= 2 && in_sizes[0] == 1) { st = (const float*)d_in[0]; X = (const float*)d_in[1]; }
    else                               { X = (const float*)d_in[0]; st = (const float*)d_in[1]; }
    float* Y = (float*)d_out;

    int rows = B_ * N_;
    prep_kernel<<<(rows * 32 + 255) / 256, 256>>>(X);

    cudaFuncSetAttribute(knn_mma_kernel,
                         cudaFuncAttributeMaxDynamicSharedMemorySize, SMEM_TOTAL);
    dim3 grid(N_ / QT, B_);
    knn_mma_kernel<<<grid, NT, SMEM_TOTAL>>>(X, st, Y);
}